// round 5
// baseline (speedup 1.0000x reference)
#include <cuda_runtime.h>
#include <cuda_bf16.h>
#include <cstdint>

typedef unsigned int u32;
typedef unsigned long long u64;
typedef __nv_bfloat16  bf16;
typedef __nv_bfloat162 bf162;

#define Hd   512
#define SPd  520
#define MTr  16384
#define PSZ  (32*SPd*Hd)
#define INTOFF 2048
#define CWL  (512*2560)
#define HWL  (1024*512)

// ---------------- static device scratch ----------------
__device__ bf16 g_pf[2][2][PSZ];      // fwd padded activations [buf][split h/m]
__device__ bf16 g_pb[2][2][PSZ];      // bwd
__device__ bf16 g_cW[2][2][3*CWL];    // conv weights [dir][split][layer][512 n][2560 k]
__device__ bf16 g_hW[2][2][6*HWL];    // hw weights   [dir][split][l*2+j][1024 q][512 k]

// ---------------- helpers ----------------
__device__ __forceinline__ u32 s2u(const void* p) {
    u32 a; asm("{ .reg .u64 t; cvta.to.shared.u64 t, %1; cvt.u32.u64 %0, t; }"
               : "=r"(a) : "l"(p)); return a;
}
__device__ __forceinline__ void cp16(u32 d, const void* s) {
    asm volatile("cp.async.cg.shared.global [%0], [%1], 16;" :: "r"(d), "l"(s) : "memory");
}
__device__ __forceinline__ void ldsm4(u32* r, u32 a) {
    asm volatile("ldmatrix.sync.aligned.m8n8.x4.shared.b16 {%0,%1,%2,%3}, [%4];"
                 : "=r"(r[0]), "=r"(r[1]), "=r"(r[2]), "=r"(r[3]) : "r"(a));
}
__device__ __forceinline__ void mma16816(float* d, const u32* a, const u32* b) {
    asm volatile("mma.sync.aligned.m16n8k16.row.col.f32.bf16.bf16.f32 "
                 "{%0,%1,%2,%3}, {%4,%5,%6,%7}, {%8,%9}, {%0,%1,%2,%3};"
                 : "+f"(d[0]), "+f"(d[1]), "+f"(d[2]), "+f"(d[3])
                 : "r"(a[0]), "r"(a[1]), "r"(a[2]), "r"(a[3]), "r"(b[0]), "r"(b[1]));
}

__device__ __forceinline__ size_t crow(int r) {
    return (size_t)(r + ((r >> 9) << 3)) * Hd;   // conv-mapped padded row
}
__device__ __forceinline__ void split2(float v0, float v1, u32& hh, u32& mm) {
    bf162 h2 = __float22bfloat162_rn(make_float2(v0, v1));
    float2 hf = __bfloat1622float2(h2);
    bf162 m2 = __float22bfloat162_rn(make_float2(v0 - hf.x, v1 - hf.y));
    hh = *(u32*)&h2; mm = *(u32*)&m2;
}
__device__ __forceinline__ void split1(float v, bf16& h, bf16& m) {
    h = __float2bfloat16_rn(v);
    m = __float2bfloat16_rn(v - __bfloat162float(h));
}
__device__ __forceinline__ u32 swz(int row, int ch) {   // 64B-row XOR swizzle
    return (u32)(row * 64 + ((ch ^ ((row >> 1) & 3)) << 4));
}

#define STAGE 32768
#define NSTG  3
#define DSM   (128 + NSTG*STAGE)

// ================= split-bf16 HMMA GEMM + register-fused epilogue =================
// C[128, 128-per-CTA] = sum_k A[m][k]*Wt[n][k], 3 split passes (AhBh+AhBm+AmBh).
// MODE 0: conv  -> relu(D+bias), split-store to Yh/Ym (conv-mapped)
// MODE 1: hw    -> gated combine with X (nl/gate adjacent cols), split-store
// MODE 2: hw    -> same + fp32 store to outp
template<int K, int MODE>
__global__ __launch_bounds__(256, 2)
void mma_gemm(const bf16* __restrict__ Ah, const bf16* __restrict__ Am,
              const bf16* __restrict__ Wh, const bf16* __restrict__ Wm,
              const float* __restrict__ bias,
              const bf16* __restrict__ Xh, const bf16* __restrict__ Xm,
              bf16* __restrict__ Yh, bf16* __restrict__ Ym,
              float* __restrict__ outp)
{
    constexpr int NC = K / 32;
    extern __shared__ char dsm[];
    const u32 base = (s2u(dsm) + 127) & ~127u;

    const int tid  = threadIdx.x;
    const int lane = tid & 31;
    const int wid  = tid >> 5;
    const int wm   = (wid >> 2) * 64;
    const int wn   = (wid & 3) * 32;
    const int m0   = blockIdx.y << 7;
    const int nb0  = blockIdx.x << 7;

    // per-thread load geometry: v = tid + it*256 over [0,1024)
    const int lpl  = tid >> 9;                 // always 0 for it<2 pattern below
    (void)lpl;
    const bf16* aSrc[4]; const bf16* bSrc[4];
    u32 aOff[4], bOff[4];
#pragma unroll
    for (int it = 0; it < 4; it++) {
        int v = tid + it * 256;
        int pl = v >> 9, rem = v & 511;
        int row = rem >> 2, ch = rem & 3;
        aSrc[it] = (pl ? Am : Ah) + crow(m0 + row) + ch * 8;
        aOff[it] = pl * 8192 + swz(row, ch);
        bSrc[it] = (pl ? Wm : Wh) + (size_t)(nb0 + row) * K + ch * 8;
        bOff[it] = 16384u + pl * 8192 + swz(row, ch);
    }

    auto load_chunk = [&](int c, int stg) {
        const u32 sb = base + (u32)(stg * STAGE);
        const int kc = c * 32;
#pragma unroll
        for (int it = 0; it < 4; it++) cp16(sb + aOff[it], aSrc[it] + kc);
#pragma unroll
        for (int it = 0; it < 4; it++) cp16(sb + bOff[it], bSrc[it] + kc);
        asm volatile("cp.async.commit_group;" ::: "memory");
    };

    float acc[4][4][4];
#pragma unroll
    for (int i = 0; i < 4; i++)
#pragma unroll
        for (int j = 0; j < 4; j++)
#pragma unroll
            for (int q = 0; q < 4; q++) acc[i][j][q] = 0.f;

    load_chunk(0, 0);
    load_chunk(1, 1);

    const int ar = lane & 15;
    const int ac = lane >> 4;
    const int br = (lane & 7) + ((lane & 16) >> 1);
    const int bc = (lane >> 3) & 1;

    int stg = 0, stg2 = 2;                     // stage of chunk c, and of c+2
    for (int c = 0; c < NC; c++) {
        asm volatile("cp.async.wait_group 1;" ::: "memory");
        __syncthreads();
        if (c + 2 < NC) load_chunk(c + 2, stg2);
        else            asm volatile("cp.async.commit_group;" ::: "memory");

        const u32 sb = base + (u32)(stg * STAGE);
#pragma unroll
        for (int s = 0; s < 2; s++) {
            u32 bf0[8], bf1[8], afr[4][4];
#pragma unroll
            for (int jp = 0; jp < 2; jp++) {
                ldsm4(&bf0[jp * 4], sb + 16384 + swz(wn + jp * 16 + br, 2 * s + bc));
                ldsm4(&bf1[jp * 4], sb + 16384 + 8192 + swz(wn + jp * 16 + br, 2 * s + bc));
            }
#pragma unroll
            for (int i = 0; i < 4; i++)
                ldsm4(afr[i], sb + swz(wm + i * 16 + ar, 2 * s + ac));
#pragma unroll
            for (int i = 0; i < 4; i++)
#pragma unroll
                for (int j = 0; j < 4; j++) {
                    mma16816(acc[i][j], afr[i], &bf0[j * 2]);   // Ah*Bh
                    mma16816(acc[i][j], afr[i], &bf1[j * 2]);   // Ah*Bm
                }
#pragma unroll
            for (int i = 0; i < 4; i++)
                ldsm4(afr[i], sb + 8192 + swz(wm + i * 16 + ar, 2 * s + ac));
#pragma unroll
            for (int i = 0; i < 4; i++)
#pragma unroll
                for (int j = 0; j < 4; j++)
                    mma16816(acc[i][j], afr[i], &bf0[j * 2]);   // Am*Bh
        }
        stg = (stg == 2) ? 0 : stg + 1;
        stg2 = (stg2 == 2) ? 0 : stg2 + 1;
    }

    // ---- register-level fused epilogue ----
    const int row0 = wm + (lane >> 2);

    if (MODE == 0) {
#pragma unroll
        for (int j = 0; j < 4; j++) {
            const int c0 = nb0 + wn + j * 8 + (lane & 3) * 2;
            const float bv0 = bias[c0], bv1 = bias[c0 + 1];
#pragma unroll
            for (int i = 0; i < 4; i++)
#pragma unroll
                for (int h = 0; h < 2; h++) {
                    const int gr = m0 + row0 + i * 16 + h * 8;
                    float v0 = fmaxf(acc[i][j][2 * h]     + bv0, 0.f);
                    float v1 = fmaxf(acc[i][j][2 * h + 1] + bv1, 0.f);
                    u32 hh, mm;
                    split2(v0, v1, hh, mm);
                    const size_t o = crow(gr) + c0;
                    *(u32*)(Yh + o) = hh;
                    *(u32*)(Ym + o) = mm;
                }
        }
    } else {
#pragma unroll
        for (int j = 0; j < 4; j++) {
            const int f = blockIdx.x * 64 + (wn >> 1) + j * 4 + (lane & 3);
            const float bn = bias[f], bg = bias[512 + f];
#pragma unroll
            for (int i = 0; i < 4; i++)
#pragma unroll
                for (int h = 0; h < 2; h++) {
                    const int gr = m0 + row0 + i * 16 + h * 8;
                    const size_t xo = crow(gr) + f;
                    float x = __bfloat162float(Xh[xo]) + __bfloat162float(Xm[xo]);
                    float nl = acc[i][j][2 * h]     + bn;
                    float gt = acc[i][j][2 * h + 1] + bg;
                    float g = 1.f / (1.f + __expf(-gt));
                    float o = g * x + (1.f - g) * fmaxf(nl, 0.f);
                    bf16 oh, om;
                    split1(o, oh, om);
                    Yh[xo] = oh;   // xo == crow(gr)+f == output offset
                    Ym[xo] = om;
                    if (MODE == 2) outp[(size_t)gr * 1024 + f] = o;
                }
        }
    }
}

// ================= prep kernels =================
__global__ void prep_convW(const float* __restrict__ W, bf16* __restrict__ Oh, bf16* __restrict__ Om) {
    // W: [3][2560][512] -> O: [3][512 n][2560 k]
    int w = (blockIdx.x * blockDim.x + threadIdx.x) >> 5;
    int lane = threadIdx.x & 31;
    int layer = w / (16 * 320); int rem = w % (16 * 320);
    int n = (rem / 320) * 32 + lane; int k0 = (rem % 320) * 8;
    const float* src = W + (size_t)layer * 2560 * 512 + (size_t)k0 * 512 + n;
    u32 hh[4], mm[4];
#pragma unroll
    for (int t = 0; t < 4; t++)
        split2(src[(2*t) * 512], src[(2*t + 1) * 512], hh[t], mm[t]);
    size_t o = ((size_t)layer * 512 + n) * 2560 + k0;
    *(uint4*)(Oh + o) = *(uint4*)hh;
    *(uint4*)(Om + o) = *(uint4*)mm;
}

__global__ void prep_hwW(const float* __restrict__ W, bf16* __restrict__ Oh, bf16* __restrict__ Om) {
    // W: [6][512][1024] -> O: [6][1024 q][512 k]
    // q layout: adjacent interleave — feature f: nl -> q=2f, gate -> q=2f+1
    int w = (blockIdx.x * blockDim.x + threadIdx.x) >> 5;
    int lane = threadIdx.x & 31;
    int lw = w / (32 * 64); int rem = w % (32 * 64);
    int np = (rem / 64) * 32 + lane; int k0 = (rem % 64) * 8;
    int q = (np < 512) ? (np * 2) : ((np - 512) * 2 + 1);
    const float* src = W + (size_t)lw * 512 * 1024 + (size_t)k0 * 1024 + np;
    u32 hh[4], mm[4];
#pragma unroll
    for (int t = 0; t < 4; t++)
        split2(src[(2*t) * 1024], src[(2*t + 1) * 1024], hh[t], mm[t]);
    size_t o = ((size_t)lw * 1024 + q) * 512 + k0;
    *(uint4*)(Oh + o) = *(uint4*)hh;
    *(uint4*)(Om + o) = *(uint4*)mm;
}

__global__ void prep_act(const float* __restrict__ in,
                         bf16* __restrict__ fh, bf16* __restrict__ fm,
                         bf16* __restrict__ bh, bf16* __restrict__ bm) {
    int idx = blockIdx.x * 256 + threadIdx.x;
    int e = idx << 2;
    int r = e >> 9, h = e & 511;
    float4 v = *(const float4*)(in + e);
    u32 hw2[2], mw2[2];
    split2(v.x, v.y, hw2[0], mw2[0]);
    split2(v.z, v.w, hw2[1], mw2[1]);
    size_t o = crow(r) + h;
    *(uint2*)(fh + o) = *(uint2*)hw2; *(uint2*)(fm + o) = *(uint2*)mw2;
    *(uint2*)(bh + o) = *(uint2*)hw2; *(uint2*)(bm + o) = *(uint2*)mw2;
}

__global__ void prep_pads(const float* __restrict__ fp, const float* __restrict__ bp,
                          bf16* __restrict__ fh, bf16* __restrict__ fm,
                          bf16* __restrict__ bh, bf16* __restrict__ bm) {
    int idx = blockIdx.x * 256 + threadIdx.x;
    int e = idx << 2;
    int b = e >> 12; int rem = e & 4095; int p = rem >> 9; int h = rem & 511;
    const float* s = (p < 4) ? (fp + p * 512 + h) : (bp + (p - 4) * 512 + h);
    int row = (p < 4) ? (b * 520 + p) : (b * 520 + 516 + (p - 4));
    float4 v = *(const float4*)s;
    u32 hw2[2], mw2[2];
    split2(v.x, v.y, hw2[0], mw2[0]);
    split2(v.z, v.w, hw2[1], mw2[1]);
    size_t o = (size_t)row * 512 + h;
    *(uint2*)(fh + o) = *(uint2*)hw2; *(uint2*)(fm + o) = *(uint2*)mw2;
    *(uint2*)(bh + o) = *(uint2*)hw2; *(uint2*)(bm + o) = *(uint2*)mw2;
}

// ================= host =================
extern "C" void kernel_launch(void* const* d_in, const int* in_sizes, int n_in,
                              void* d_out, int out_size)
{
    const float* inputs   = (const float*)d_in[0];
    const float* fwd_pads = (const float*)d_in[2];
    const float* bwd_pads = (const float*)d_in[3];
    const float* fwd_W    = (const float*)d_in[4];
    const float* fwd_bi   = (const float*)d_in[5];
    const float* bwd_W    = (const float*)d_in[6];
    const float* bwd_bi   = (const float*)d_in[7];
    const float* fwd_hw_W = (const float*)d_in[8];
    const float* fwd_hw_b = (const float*)d_in[9];
    const float* bwd_hw_W = (const float*)d_in[10];
    const float* bwd_hw_b = (const float*)d_in[11];
    float* out = (float*)d_out;

    bf16 *pfB, *pbB, *cwB, *hwB;
    cudaGetSymbolAddress((void**)&pfB, g_pf);
    cudaGetSymbolAddress((void**)&pbB, g_pb);
    cudaGetSymbolAddress((void**)&cwB, g_cW);
    cudaGetSymbolAddress((void**)&hwB, g_hW);
    bf16 *pfh[2] = { pfB,                 pfB + 2*(size_t)PSZ };
    bf16 *pfm[2] = { pfB + PSZ,           pfB + 3*(size_t)PSZ };
    bf16 *pbh[2] = { pbB,                 pbB + 2*(size_t)PSZ };
    bf16 *pbm[2] = { pbB + PSZ,           pbB + 3*(size_t)PSZ };
    bf16 *cwh[2] = { cwB,                 cwB + 2*(size_t)(3*CWL) };
    bf16 *cwm[2] = { cwB + 3*(size_t)CWL, cwB + 3*(size_t)(3*CWL) };
    bf16 *hwh[2] = { hwB,                 hwB + 2*(size_t)(6*HWL) };
    bf16 *hwm[2] = { hwB + 6*(size_t)HWL, hwB + 3*(size_t)(6*HWL) };

    static int inited = 0;
    if (!inited) {
        cudaFuncSetAttribute(mma_gemm<2560,0>, cudaFuncAttributeMaxDynamicSharedMemorySize, DSM);
        cudaFuncSetAttribute(mma_gemm<512,1>,  cudaFuncAttributeMaxDynamicSharedMemorySize, DSM);
        cudaFuncSetAttribute(mma_gemm<512,2>,  cudaFuncAttributeMaxDynamicSharedMemorySize, DSM);
        inited = 1;
    }

    prep_convW<<<1920, 256>>>(fwd_W, cwh[0], cwm[0]);
    prep_convW<<<1920, 256>>>(bwd_W, cwh[1], cwm[1]);
    prep_hwW<<<1536, 256>>>(fwd_hw_W, hwh[0], hwm[0]);
    prep_hwW<<<1536, 256>>>(bwd_hw_W, hwh[1], hwm[1]);
    prep_act<<<8192, 256>>>(inputs, pfh[0] + INTOFF, pfm[0] + INTOFF,
                                    pbh[0] + INTOFF, pbm[0] + INTOFF);

    int c = 0;
    for (int l = 0; l < 3; l++) {
        const int d = 1 - c;
        prep_pads<<<128, 256>>>(fwd_pads + (size_t)l * 2048, bwd_pads + (size_t)l * 2048,
                                pfh[c], pfm[c], pbh[c], pbm[c]);

        // conv: buf[c] (padded) -> buf[d] interior, relu+bias
        mma_gemm<2560,0><<<dim3(4,128), 256, DSM>>>(
            pfh[c], pfm[c], cwh[0] + (size_t)l*CWL, cwm[0] + (size_t)l*CWL,
            fwd_bi + (size_t)l*512, nullptr, nullptr,
            pfh[d] + INTOFF, pfm[d] + INTOFF, nullptr);
        mma_gemm<2560,0><<<dim3(4,128), 256, DSM>>>(
            pbh[c] + 2048, pbm[c] + 2048, cwh[1] + (size_t)l*CWL, cwm[1] + (size_t)l*CWL,
            bwd_bi + (size_t)l*512, nullptr, nullptr,
            pbh[d] + INTOFF, pbm[d] + INTOFF, nullptr);

        // hw1: buf[d] -> buf[c]
        mma_gemm<512,1><<<dim3(8,128), 256, DSM>>>(
            pfh[d] + INTOFF, pfm[d] + INTOFF,
            hwh[0] + (size_t)(l*2)*HWL, hwm[0] + (size_t)(l*2)*HWL,
            fwd_hw_b + (size_t)(l*2)*1024,
            pfh[d] + INTOFF, pfm[d] + INTOFF,
            pfh[c] + INTOFF, pfm[c] + INTOFF, nullptr);
        mma_gemm<512,1><<<dim3(8,128), 256, DSM>>>(
            pbh[d] + INTOFF, pbm[d] + INTOFF,
            hwh[1] + (size_t)(l*2)*HWL, hwm[1] + (size_t)(l*2)*HWL,
            bwd_hw_b + (size_t)(l*2)*1024,
            pbh[d] + INTOFF, pbm[d] + INTOFF,
            pbh[c] + INTOFF, pbm[c] + INTOFF, nullptr);

        // hw2: buf[c] -> buf[d], + fp32 output
        mma_gemm<512,2><<<dim3(8,128), 256, DSM>>>(
            pfh[c] + INTOFF, pfm[c] + INTOFF,
            hwh[0] + (size_t)(l*2+1)*HWL, hwm[0] + (size_t)(l*2+1)*HWL,
            fwd_hw_b + (size_t)(l*2+1)*1024,
            pfh[c] + INTOFF, pfm[c] + INTOFF,
            pfh[d] + INTOFF, pfm[d] + INTOFF,
            out + (size_t)l * MTr * 1024);
        mma_gemm<512,2><<<dim3(8,128), 256, DSM>>>(
            pbh[c] + INTOFF, pbm[c] + INTOFF,
            hwh[1] + (size_t)(l*2+1)*HWL, hwm[1] + (size_t)(l*2+1)*HWL,
            bwd_hw_b + (size_t)(l*2+1)*1024,
            pbh[c] + INTOFF, pbm[c] + INTOFF,
            pbh[d] + INTOFF, pbm[d] + INTOFF,
            out + (size_t)l * MTr * 1024 + 512);

        c = d;
    }
}

// round 6
// speedup vs baseline: 1.5485x; 1.5485x over previous
#include <cuda_runtime.h>
#include <cuda_bf16.h>
#include <cstdint>

typedef unsigned int u32;
typedef unsigned long long u64;
typedef __nv_bfloat16  bf16;
typedef __nv_bfloat162 bf162;

#define Hd   512
#define SPd  520
#define MTr  16384
#define PSZ  (32*SPd*Hd)
#define INTOFF 2048
#define CWL  (512*2560)
#define HWL  (1024*512)

// ---------------- static device scratch ----------------
__device__ bf16 g_pf[2][2][PSZ];      // fwd padded activations [buf][split h/m]
__device__ bf16 g_pb[2][2][PSZ];      // bwd
__device__ bf16 g_cW[2][2][3*CWL];    // conv weights [dir][split][layer][512 n][2560 k]
__device__ bf16 g_hW[2][2][6*HWL];    // hw weights   [dir][split][l*2+j][1024 q][512 k]

// ---------------- helpers ----------------
__device__ __forceinline__ u32 s2u(const void* p) {
    u32 a; asm("{ .reg .u64 t; cvta.to.shared.u64 t, %1; cvt.u32.u64 %0, t; }"
               : "=r"(a) : "l"(p)); return a;
}
__device__ __forceinline__ void cp16(u32 d, const void* s) {
    asm volatile("cp.async.cg.shared.global [%0], [%1], 16;" :: "r"(d), "l"(s) : "memory");
}
__device__ __forceinline__ void ldsm4(u32* r, u32 a) {
    asm volatile("ldmatrix.sync.aligned.m8n8.x4.shared.b16 {%0,%1,%2,%3}, [%4];"
                 : "=r"(r[0]), "=r"(r[1]), "=r"(r[2]), "=r"(r[3]) : "r"(a));
}
__device__ __forceinline__ void mma16816(float* d, const u32* a, const u32* b) {
    asm volatile("mma.sync.aligned.m16n8k16.row.col.f32.bf16.bf16.f32 "
                 "{%0,%1,%2,%3}, {%4,%5,%6,%7}, {%8,%9}, {%0,%1,%2,%3};"
                 : "+f"(d[0]), "+f"(d[1]), "+f"(d[2]), "+f"(d[3])
                 : "r"(a[0]), "r"(a[1]), "r"(a[2]), "r"(a[3]), "r"(b[0]), "r"(b[1]));
}

__device__ __forceinline__ size_t crow(int r) {
    return (size_t)(r + ((r >> 9) << 3)) * Hd;   // conv-mapped padded row
}
__device__ __forceinline__ void split2(float v0, float v1, u32& hh, u32& mm) {
    bf162 h2 = __float22bfloat162_rn(make_float2(v0, v1));
    float2 hf = __bfloat1622float2(h2);
    bf162 m2 = __float22bfloat162_rn(make_float2(v0 - hf.x, v1 - hf.y));
    hh = *(u32*)&h2; mm = *(u32*)&m2;
}
__device__ __forceinline__ u32 swz(int row, int ch) {   // 64B-row XOR swizzle
    return (u32)(row * 64 + ((ch ^ ((row >> 1) & 3)) << 4));
}

#define STAGE 32768
#define NSTG  3
#define DSM   (128 + NSTG*STAGE)     // staging buffer (67.6KB) unions with stages

// ================= split-bf16 HMMA GEMM + fused epilogue =================
// C[128, 128-per-CTA] = sum_k A[m][k]*Wt[n][k], 3 split passes (AhBh+AhBm+AmBh).
// MODE 0: conv  -> relu(D+bias), split-store to Yh/Ym (conv-mapped)
// MODE 1: hw    -> gated combine with X (64-block nl/gate interleave), split-store
// MODE 2: hw    -> same + fp32 store to outp
template<int K, int MODE>
__global__ __launch_bounds__(256, 2)
void mma_gemm(const bf16* __restrict__ Ah, const bf16* __restrict__ Am,
              const bf16* __restrict__ Wh, const bf16* __restrict__ Wm,
              const float* __restrict__ bias,
              const bf16* __restrict__ Xh, const bf16* __restrict__ Xm,
              bf16* __restrict__ Yh, bf16* __restrict__ Ym,
              float* __restrict__ outp)
{
    constexpr int NC = K / 32;
    extern __shared__ char dsm[];
    const u32 base = (s2u(dsm) + 127) & ~127u;
    float* sstg = (float*)(dsm + (base - s2u(dsm)));   // UNION with pipeline stages

    const int tid  = threadIdx.x;
    const int lane = tid & 31;
    const int wid  = tid >> 5;
    const int wm   = (wid >> 2) * 64;
    const int wn   = (wid & 3) * 32;
    const int m0   = blockIdx.y << 7;
    const int nb0  = blockIdx.x << 7;

    const bf16* aSrc[4]; const bf16* bSrc[4];
    u32 aOff[4], bOff[4];
#pragma unroll
    for (int it = 0; it < 4; it++) {
        int v = tid + it * 256;
        int pl = v >> 9, rem = v & 511;
        int row = rem >> 2, ch = rem & 3;
        aSrc[it] = (pl ? Am : Ah) + crow(m0 + row) + ch * 8;
        aOff[it] = pl * 8192 + swz(row, ch);
        bSrc[it] = (pl ? Wm : Wh) + (size_t)(nb0 + row) * K + ch * 8;
        bOff[it] = 16384u + pl * 8192 + swz(row, ch);
    }

    auto load_chunk = [&](int c, int stg) {
        const u32 sb = base + (u32)(stg * STAGE);
        const int kc = c * 32;
#pragma unroll
        for (int it = 0; it < 4; it++) cp16(sb + aOff[it], aSrc[it] + kc);
#pragma unroll
        for (int it = 0; it < 4; it++) cp16(sb + bOff[it], bSrc[it] + kc);
        asm volatile("cp.async.commit_group;" ::: "memory");
    };

    float acc[4][4][4];
#pragma unroll
    for (int i = 0; i < 4; i++)
#pragma unroll
        for (int j = 0; j < 4; j++)
#pragma unroll
            for (int q = 0; q < 4; q++) acc[i][j][q] = 0.f;

    load_chunk(0, 0);
    load_chunk(1, 1);

    const int ar = lane & 15;
    const int ac = lane >> 4;
    const int br = (lane & 7) + ((lane & 16) >> 1);
    const int bc = (lane >> 3) & 1;

    int stg = 0, stg2 = 2;
    for (int c = 0; c < NC; c++) {
        asm volatile("cp.async.wait_group 1;" ::: "memory");
        __syncthreads();
        if (c + 2 < NC) load_chunk(c + 2, stg2);
        else            asm volatile("cp.async.commit_group;" ::: "memory");

        const u32 sb = base + (u32)(stg * STAGE);
#pragma unroll
        for (int s = 0; s < 2; s++) {
            u32 bf0[8], bf1[8], afr[4][4];
#pragma unroll
            for (int jp = 0; jp < 2; jp++) {
                ldsm4(&bf0[jp * 4], sb + 16384 + swz(wn + jp * 16 + br, 2 * s + bc));
                ldsm4(&bf1[jp * 4], sb + 16384 + 8192 + swz(wn + jp * 16 + br, 2 * s + bc));
            }
#pragma unroll
            for (int i = 0; i < 4; i++)
                ldsm4(afr[i], sb + swz(wm + i * 16 + ar, 2 * s + ac));
#pragma unroll
            for (int i = 0; i < 4; i++)
#pragma unroll
                for (int j = 0; j < 4; j++) {
                    mma16816(acc[i][j], afr[i], &bf0[j * 2]);   // Ah*Bh
                    mma16816(acc[i][j], afr[i], &bf1[j * 2]);   // Ah*Bm
                }
#pragma unroll
            for (int i = 0; i < 4; i++)
                ldsm4(afr[i], sb + 8192 + swz(wm + i * 16 + ar, 2 * s + ac));
#pragma unroll
            for (int i = 0; i < 4; i++)
#pragma unroll
                for (int j = 0; j < 4; j++)
                    mma16816(acc[i][j], afr[i], &bf0[j * 2]);   // Am*Bh
        }
        stg  = (stg == 2)  ? 0 : stg + 1;
        stg2 = (stg2 == 2) ? 0 : stg2 + 1;
    }

    // ---- stage accumulators to smem (pipeline smem now dead) ----
    __syncthreads();
#pragma unroll
    for (int i = 0; i < 4; i++)
#pragma unroll
        for (int j = 0; j < 4; j++) {
            int r0 = wm + i * 16 + (lane >> 2);
            int cc = wn + j * 8 + (lane & 3) * 2;
            *(float2*)&sstg[r0 * 132 + cc]       = make_float2(acc[i][j][0], acc[i][j][1]);
            *(float2*)&sstg[(r0 + 8) * 132 + cc] = make_float2(acc[i][j][2], acc[i][j][3]);
        }
    __syncthreads();

    // ---- fused, coalesced epilogue ----
    const int r  = tid >> 1;
    const int gr = m0 + r;

    if (MODE == 0) {
        const int c0 = (tid & 1) * 64;
#pragma unroll
        for (int c8 = 0; c8 < 8; c8++) {
            const int cb = c0 + c8 * 8;
            u32 hh[4], mm[4];
#pragma unroll
            for (int t = 0; t < 4; t++) {
                float v0 = fmaxf(sstg[r * 132 + cb + 2*t]     + bias[nb0 + cb + 2*t],     0.f);
                float v1 = fmaxf(sstg[r * 132 + cb + 2*t + 1] + bias[nb0 + cb + 2*t + 1], 0.f);
                split2(v0, v1, hh[t], mm[t]);
            }
            const size_t o = crow(gr) + nb0 + cb;
            *(uint4*)(Yh + o) = *(uint4*)hh;
            *(uint4*)(Ym + o) = *(uint4*)mm;
        }
    } else {
        const int fbase = blockIdx.x * 64;
        const int fl0   = (tid & 1) * 32;
#pragma unroll
        for (int c8 = 0; c8 < 4; c8++) {
            const int fl = fl0 + c8 * 8;
            const int f  = fbase + fl;
            uint4 xh4 = *(const uint4*)(Xh + crow(gr) + f);
            uint4 xm4 = *(const uint4*)(Xm + crow(gr) + f);
            u32 hh[4], mm[4];
            float ov[8];
#pragma unroll
            for (int t = 0; t < 4; t++) {
                float2 xh2 = __bfloat1622float2(*(bf162*)&((u32*)&xh4)[t]);
                float2 xm2 = __bfloat1622float2(*(bf162*)&((u32*)&xm4)[t]);
                float x0 = xh2.x + xm2.x, x1 = xh2.y + xm2.y;
                float nl0 = sstg[r * 132 + fl + 2*t]       + bias[f + 2*t];
                float nl1 = sstg[r * 132 + fl + 2*t + 1]   + bias[f + 2*t + 1];
                float gt0 = sstg[r * 132 + 64 + fl + 2*t]     + bias[512 + f + 2*t];
                float gt1 = sstg[r * 132 + 64 + fl + 2*t + 1] + bias[512 + f + 2*t + 1];
                float s0 = 1.f / (1.f + __expf(-gt0));
                float s1 = 1.f / (1.f + __expf(-gt1));
                float o0 = s0 * x0 + (1.f - s0) * fmaxf(nl0, 0.f);
                float o1 = s1 * x1 + (1.f - s1) * fmaxf(nl1, 0.f);
                split2(o0, o1, hh[t], mm[t]);
                ov[2*t] = o0; ov[2*t + 1] = o1;
            }
            const size_t yo = crow(gr) + f;
            *(uint4*)(Yh + yo) = *(uint4*)hh;
            *(uint4*)(Ym + yo) = *(uint4*)mm;
            if (MODE == 2) {
                *(float4*)(outp + (size_t)gr * 1024 + f)     = *(float4*)&ov[0];
                *(float4*)(outp + (size_t)gr * 1024 + f + 4) = *(float4*)&ov[4];
            }
        }
    }
}

// ================= prep kernels =================
__global__ void prep_convW(const float* __restrict__ W, bf16* __restrict__ Oh, bf16* __restrict__ Om) {
    // W: [3][2560][512] -> O: [3][512 n][2560 k]
    int w = (blockIdx.x * blockDim.x + threadIdx.x) >> 5;
    int lane = threadIdx.x & 31;
    int layer = w / (16 * 320); int rem = w % (16 * 320);
    int n = (rem / 320) * 32 + lane; int k0 = (rem % 320) * 8;
    const float* src = W + (size_t)layer * 2560 * 512 + (size_t)k0 * 512 + n;
    u32 hh[4], mm[4];
#pragma unroll
    for (int t = 0; t < 4; t++)
        split2(src[(2*t) * 512], src[(2*t + 1) * 512], hh[t], mm[t]);
    size_t o = ((size_t)layer * 512 + n) * 2560 + k0;
    *(uint4*)(Oh + o) = *(uint4*)hh;
    *(uint4*)(Om + o) = *(uint4*)mm;
}

__global__ void prep_hwW(const float* __restrict__ W, bf16* __restrict__ Oh, bf16* __restrict__ Om) {
    // W: [6][512][1024] -> O: [6][1024 q][512 k]
    // q layout: block fb (0..7) covers cols [fb*128, fb*128+128):
    //   cols 0-63 = nl features fb*64.., cols 64-127 = gate features fb*64..
    int w = (blockIdx.x * blockDim.x + threadIdx.x) >> 5;
    int lane = threadIdx.x & 31;
    int lw = w / (32 * 64); int rem = w % (32 * 64);
    int np = (rem / 64) * 32 + lane; int k0 = (rem % 64) * 8;
    int f = (np < 512) ? np : (np - 512);
    int q = (f >> 6) * 128 + ((np < 512) ? (f & 63) : (64 + (f & 63)));
    const float* src = W + (size_t)lw * 512 * 1024 + (size_t)k0 * 1024 + np;
    u32 hh[4], mm[4];
#pragma unroll
    for (int t = 0; t < 4; t++)
        split2(src[(2*t) * 1024], src[(2*t + 1) * 1024], hh[t], mm[t]);
    size_t o = ((size_t)lw * 1024 + q) * 512 + k0;
    *(uint4*)(Oh + o) = *(uint4*)hh;
    *(uint4*)(Om + o) = *(uint4*)mm;
}

__global__ void prep_act(const float* __restrict__ in,
                         bf16* __restrict__ fh, bf16* __restrict__ fm,
                         bf16* __restrict__ bh, bf16* __restrict__ bm) {
    int idx = blockIdx.x * 256 + threadIdx.x;
    int e = idx << 2;
    int r = e >> 9, h = e & 511;
    float4 v = *(const float4*)(in + e);
    u32 hw2[2], mw2[2];
    split2(v.x, v.y, hw2[0], mw2[0]);
    split2(v.z, v.w, hw2[1], mw2[1]);
    size_t o = crow(r) + h;
    *(uint2*)(fh + o) = *(uint2*)hw2; *(uint2*)(fm + o) = *(uint2*)mw2;
    *(uint2*)(bh + o) = *(uint2*)hw2; *(uint2*)(bm + o) = *(uint2*)mw2;
}

__global__ void prep_pads(const float* __restrict__ fp, const float* __restrict__ bp,
                          bf16* __restrict__ fh, bf16* __restrict__ fm,
                          bf16* __restrict__ bh, bf16* __restrict__ bm) {
    int idx = blockIdx.x * 256 + threadIdx.x;
    int e = idx << 2;
    int b = e >> 12; int rem = e & 4095; int p = rem >> 9; int h = rem & 511;
    const float* s = (p < 4) ? (fp + p * 512 + h) : (bp + (p - 4) * 512 + h);
    int row = (p < 4) ? (b * 520 + p) : (b * 520 + 516 + (p - 4));
    float4 v = *(const float4*)s;
    u32 hw2[2], mw2[2];
    split2(v.x, v.y, hw2[0], mw2[0]);
    split2(v.z, v.w, hw2[1], mw2[1]);
    size_t o = (size_t)row * 512 + h;
    *(uint2*)(fh + o) = *(uint2*)hw2; *(uint2*)(fm + o) = *(uint2*)mw2;
    *(uint2*)(bh + o) = *(uint2*)hw2; *(uint2*)(bm + o) = *(uint2*)mw2;
}

// ================= host =================
extern "C" void kernel_launch(void* const* d_in, const int* in_sizes, int n_in,
                              void* d_out, int out_size)
{
    const float* inputs   = (const float*)d_in[0];
    const float* fwd_pads = (const float*)d_in[2];
    const float* bwd_pads = (const float*)d_in[3];
    const float* fwd_W    = (const float*)d_in[4];
    const float* fwd_bi   = (const float*)d_in[5];
    const float* bwd_W    = (const float*)d_in[6];
    const float* bwd_bi   = (const float*)d_in[7];
    const float* fwd_hw_W = (const float*)d_in[8];
    const float* fwd_hw_b = (const float*)d_in[9];
    const float* bwd_hw_W = (const float*)d_in[10];
    const float* bwd_hw_b = (const float*)d_in[11];
    float* out = (float*)d_out;

    bf16 *pfB, *pbB, *cwB, *hwB;
    cudaGetSymbolAddress((void**)&pfB, g_pf);
    cudaGetSymbolAddress((void**)&pbB, g_pb);
    cudaGetSymbolAddress((void**)&cwB, g_cW);
    cudaGetSymbolAddress((void**)&hwB, g_hW);
    bf16 *pfh[2] = { pfB,                 pfB + 2*(size_t)PSZ };
    bf16 *pfm[2] = { pfB + PSZ,           pfB + 3*(size_t)PSZ };
    bf16 *pbh[2] = { pbB,                 pbB + 2*(size_t)PSZ };
    bf16 *pbm[2] = { pbB + PSZ,           pbB + 3*(size_t)PSZ };
    bf16 *cwh[2] = { cwB,                 cwB + 2*(size_t)(3*CWL) };
    bf16 *cwm[2] = { cwB + 3*(size_t)CWL, cwB + 3*(size_t)(3*CWL) };
    bf16 *hwh[2] = { hwB,                 hwB + 2*(size_t)(6*HWL) };
    bf16 *hwm[2] = { hwB + 6*(size_t)HWL, hwB + 3*(size_t)(6*HWL) };

    static int inited = 0;
    if (!inited) {
        cudaFuncSetAttribute(mma_gemm<2560,0>, cudaFuncAttributeMaxDynamicSharedMemorySize, DSM);
        cudaFuncSetAttribute(mma_gemm<512,1>,  cudaFuncAttributeMaxDynamicSharedMemorySize, DSM);
        cudaFuncSetAttribute(mma_gemm<512,2>,  cudaFuncAttributeMaxDynamicSharedMemorySize, DSM);
        inited = 1;
    }

    prep_convW<<<1920, 256>>>(fwd_W, cwh[0], cwm[0]);
    prep_convW<<<1920, 256>>>(bwd_W, cwh[1], cwm[1]);
    prep_hwW<<<1536, 256>>>(fwd_hw_W, hwh[0], hwm[0]);
    prep_hwW<<<1536, 256>>>(bwd_hw_W, hwh[1], hwm[1]);
    prep_act<<<8192, 256>>>(inputs, pfh[0] + INTOFF, pfm[0] + INTOFF,
                                    pbh[0] + INTOFF, pbm[0] + INTOFF);

    int c = 0;
    for (int l = 0; l < 3; l++) {
        const int d = 1 - c;
        prep_pads<<<128, 256>>>(fwd_pads + (size_t)l * 2048, bwd_pads + (size_t)l * 2048,
                                pfh[c], pfm[c], pbh[c], pbm[c]);

        // conv: buf[c] (padded) -> buf[d] interior, relu+bias
        mma_gemm<2560,0><<<dim3(4,128), 256, DSM>>>(
            pfh[c], pfm[c], cwh[0] + (size_t)l*CWL, cwm[0] + (size_t)l*CWL,
            fwd_bi + (size_t)l*512, nullptr, nullptr,
            pfh[d] + INTOFF, pfm[d] + INTOFF, nullptr);
        mma_gemm<2560,0><<<dim3(4,128), 256, DSM>>>(
            pbh[c] + 2048, pbm[c] + 2048, cwh[1] + (size_t)l*CWL, cwm[1] + (size_t)l*CWL,
            bwd_bi + (size_t)l*512, nullptr, nullptr,
            pbh[d] + INTOFF, pbm[d] + INTOFF, nullptr);

        // hw1: buf[d] -> buf[c]
        mma_gemm<512,1><<<dim3(8,128), 256, DSM>>>(
            pfh[d] + INTOFF, pfm[d] + INTOFF,
            hwh[0] + (size_t)(l*2)*HWL, hwm[0] + (size_t)(l*2)*HWL,
            fwd_hw_b + (size_t)(l*2)*1024,
            pfh[d] + INTOFF, pfm[d] + INTOFF,
            pfh[c] + INTOFF, pfm[c] + INTOFF, nullptr);
        mma_gemm<512,1><<<dim3(8,128), 256, DSM>>>(
            pbh[d] + INTOFF, pbm[d] + INTOFF,
            hwh[1] + (size_t)(l*2)*HWL, hwm[1] + (size_t)(l*2)*HWL,
            bwd_hw_b + (size_t)(l*2)*1024,
            pbh[d] + INTOFF, pbm[d] + INTOFF,
            pbh[c] + INTOFF, pbm[c] + INTOFF, nullptr);

        // hw2: buf[c] -> buf[d], + fp32 output
        mma_gemm<512,2><<<dim3(8,128), 256, DSM>>>(
            pfh[c] + INTOFF, pfm[c] + INTOFF,
            hwh[0] + (size_t)(l*2+1)*HWL, hwm[0] + (size_t)(l*2+1)*HWL,
            fwd_hw_b + (size_t)(l*2+1)*1024,
            pfh[c] + INTOFF, pfm[c] + INTOFF,
            pfh[d] + INTOFF, pfm[d] + INTOFF,
            out + (size_t)l * MTr * 1024);
        mma_gemm<512,2><<<dim3(8,128), 256, DSM>>>(
            pbh[c] + INTOFF, pbm[c] + INTOFF,
            hwh[1] + (size_t)(l*2+1)*HWL, hwm[1] + (size_t)(l*2+1)*HWL,
            bwd_hw_b + (size_t)(l*2+1)*1024,
            pbh[c] + INTOFF, pbm[c] + INTOFF,
            pbh[d] + INTOFF, pbm[d] + INTOFF,
            out + (size_t)l * MTr * 1024 + 512);

        c = d;
    }
}

// round 9
// speedup vs baseline: 2.3327x; 1.5064x over previous
#include <cuda_runtime.h>
#include <cuda_fp16.h>
#include <cstdint>

typedef unsigned int u32;
typedef unsigned long long u64;

#define Hd   512
#define SPd  520
#define MTr  16384
#define PSZ  (32*SPd*Hd)
#define INTOFF 2048
#define CWL  (512*2560)
#define HWL  (1024*512)

// ---------------- static device scratch ----------------
__device__ __half g_pf[2][2][PSZ];    // fwd padded activations [buf][split h/m]
__device__ __half g_pb[2][2][PSZ];    // bwd
__device__ __half g_cW[2][3*CWL];     // conv weights [dir][layer][512 n][2560 k]  (single plane)
__device__ __half g_hW[2][6*HWL];     // hw weights   [dir][l*2+j][1024 q][512 k]

// ---------------- helpers ----------------
__device__ __forceinline__ u32 s2u(const void* p) {
    u32 a; asm("{ .reg .u64 t; cvta.to.shared.u64 t, %1; cvt.u32.u64 %0, t; }"
               : "=r"(a) : "l"(p)); return a;
}
__device__ __forceinline__ void cp16(u32 d, const void* s) {
    asm volatile("cp.async.cg.shared.global [%0], [%1], 16;" :: "r"(d), "l"(s) : "memory");
}
__device__ __forceinline__ void ldsm4(u32* r, u32 a) {
    asm volatile("ldmatrix.sync.aligned.m8n8.x4.shared.b16 {%0,%1,%2,%3}, [%4];"
                 : "=r"(r[0]), "=r"(r[1]), "=r"(r[2]), "=r"(r[3]) : "r"(a));
}
__device__ __forceinline__ void mma16816(float* d, const u32* a, const u32* b) {
    asm volatile("mma.sync.aligned.m16n8k16.row.col.f32.f16.f16.f32 "
                 "{%0,%1,%2,%3}, {%4,%5,%6,%7}, {%8,%9}, {%0,%1,%2,%3};"
                 : "+f"(d[0]), "+f"(d[1]), "+f"(d[2]), "+f"(d[3])
                 : "r"(a[0]), "r"(a[1]), "r"(a[2]), "r"(a[3]), "r"(b[0]), "r"(b[1]));
}

__device__ __forceinline__ size_t crow(int r) {
    return (size_t)(r + ((r >> 9) << 3)) * Hd;   // conv-mapped padded row
}
// fp16 (h,m) split: h = fp16(v), m = fp16(v - h)  (residual to ~2^-22)
__device__ __forceinline__ void split2h(float v0, float v1, u32& hh, u32& mm) {
    __half2 h2 = __float22half2_rn(make_float2(v0, v1));
    float2 hf = __half22float2(h2);
    __half2 m2 = __float22half2_rn(make_float2(v0 - hf.x, v1 - hf.y));
    hh = *(u32*)&h2; mm = *(u32*)&m2;
}
__device__ __forceinline__ u32 swz(int row, int ch) {   // 64B-row XOR swizzle
    return (u32)(row * 64 + ((ch ^ ((row >> 1) & 3)) << 4));
}

#define STAGE 24576            // A: 2 planes x 8KB, B: 1 plane x 8KB
#define NSTG  4
#define DSM   (128 + NSTG*STAGE)   // 96.1KB; epilogue staging (67.6KB) unions in

struct GemmArgs {
    const __half* Ah[2]; const __half* Am[2];
    const __half* W[2];  const float*  bias[2];
    const __half* Xh[2]; const __half* Xm[2];
    __half* Yh[2]; __half* Ym[2];
    float*  outp[2];
};

// ================= split-fp16 HMMA GEMM + fused epilogue =================
// 2 passes: Ah*W + Am*W (A split fp16, W single fp16), fp32 accumulate.
// MODE 0: conv -> relu(D+bias), split-store to Yh/Ym (conv-mapped)
// MODE 1: hw   -> gated combine with X (64-block nl/gate interleave), split-store
// MODE 2: hw   -> same + fp32 store to outp
template<int K, int MODE>
__global__ __launch_bounds__(256, 2)
void mma_gemm(GemmArgs g)
{
    constexpr int NC = K / 32;
    extern __shared__ char dsm[];
    const u32 base = (s2u(dsm) + 127) & ~127u;
    float* sstg = (float*)(dsm + (base - s2u(dsm)));   // UNION with pipeline stages

    const int z = blockIdx.z;
    const __half* __restrict__ Ah = g.Ah[z];
    const __half* __restrict__ Am = g.Am[z];
    const __half* __restrict__ W  = g.W[z];
    const float*  __restrict__ bias = g.bias[z];

    const int tid  = threadIdx.x;
    const int lane = tid & 31;
    const int wid  = tid >> 5;
    const int wm   = (wid >> 2) * 64;
    const int wn   = (wid & 3) * 32;
    const int m0   = blockIdx.y << 7;
    const int nb0  = blockIdx.x << 7;

    // A: 1024 16B transfers/stage (4/thread), B: 512 (2/thread)
    const __half* aSrc[4]; u32 aOff[4];
    const __half* bSrc[2]; u32 bOff[2];
#pragma unroll
    for (int it = 0; it < 4; it++) {
        int v = tid + it * 256;
        int pl = v >> 9, rem = v & 511;
        int row = rem >> 2, ch = rem & 3;
        aSrc[it] = (pl ? Am : Ah) + crow(m0 + row) + ch * 8;
        aOff[it] = pl * 8192 + swz(row, ch);
    }
#pragma unroll
    for (int it = 0; it < 2; it++) {
        int v = tid + it * 256;
        int row = v >> 2, ch = v & 3;
        bSrc[it] = W + (size_t)(nb0 + row) * K + ch * 8;
        bOff[it] = 16384u + swz(row, ch);
    }

    auto load_chunk = [&](int c) {
        const u32 sb = base + (u32)((c & 3) * STAGE);
        const int kc = c * 32;
#pragma unroll
        for (int it = 0; it < 4; it++) cp16(sb + aOff[it], aSrc[it] + kc);
#pragma unroll
        for (int it = 0; it < 2; it++) cp16(sb + bOff[it], bSrc[it] + kc);
        asm volatile("cp.async.commit_group;" ::: "memory");
    };

    float acc[4][4][4];
#pragma unroll
    for (int i = 0; i < 4; i++)
#pragma unroll
        for (int j = 0; j < 4; j++)
#pragma unroll
            for (int q = 0; q < 4; q++) acc[i][j][q] = 0.f;

    load_chunk(0); load_chunk(1); load_chunk(2);

    const int ar = lane & 15;
    const int ac = lane >> 4;
    const int br = (lane & 7) + ((lane & 16) >> 1);
    const int bc = (lane >> 3) & 1;

    for (int c = 0; c < NC; c++) {
        asm volatile("cp.async.wait_group 2;" ::: "memory");
        __syncthreads();
        if (c + 3 < NC) load_chunk(c + 3);
        else            asm volatile("cp.async.commit_group;" ::: "memory");

        const u32 sb = base + (u32)((c & 3) * STAGE);
#pragma unroll
        for (int s = 0; s < 2; s++) {
            u32 bfb[8], afr[4][4];
            ldsm4(&bfb[0], sb + 16384 + swz(wn + br, 2 * s + bc));
            ldsm4(&bfb[4], sb + 16384 + swz(wn + 16 + br, 2 * s + bc));
#pragma unroll
            for (int i = 0; i < 4; i++)
                ldsm4(afr[i], sb + swz(wm + i * 16 + ar, 2 * s + ac));
#pragma unroll
            for (int i = 0; i < 4; i++)
#pragma unroll
                for (int j = 0; j < 4; j++)
                    mma16816(acc[i][j], afr[i], &bfb[j * 2]);   // Ah*W
#pragma unroll
            for (int i = 0; i < 4; i++)
                ldsm4(afr[i], sb + 8192 + swz(wm + i * 16 + ar, 2 * s + ac));
#pragma unroll
            for (int i = 0; i < 4; i++)
#pragma unroll
                for (int j = 0; j < 4; j++)
                    mma16816(acc[i][j], afr[i], &bfb[j * 2]);   // Am*W
        }
    }

    // ---- stage accumulators to smem (pipeline smem now dead) ----
    __syncthreads();
#pragma unroll
    for (int i = 0; i < 4; i++)
#pragma unroll
        for (int j = 0; j < 4; j++) {
            int r0 = wm + i * 16 + (lane >> 2);
            int cc = wn + j * 8 + (lane & 3) * 2;
            *(float2*)&sstg[r0 * 132 + cc]       = make_float2(acc[i][j][0], acc[i][j][1]);
            *(float2*)&sstg[(r0 + 8) * 132 + cc] = make_float2(acc[i][j][2], acc[i][j][3]);
        }
    __syncthreads();

    // ---- fused, coalesced epilogue ----
    const int r  = tid >> 1;
    const int gr = m0 + r;
    __half* Yh = g.Yh[z]; __half* Ym = g.Ym[z];

    if (MODE == 0) {
        const int c0 = (tid & 1) * 64;
#pragma unroll
        for (int c8 = 0; c8 < 8; c8++) {
            const int cb = c0 + c8 * 8;
            u32 hh[4], mm[4];
#pragma unroll
            for (int t = 0; t < 4; t++) {
                float v0 = fmaxf(sstg[r * 132 + cb + 2*t]     + bias[nb0 + cb + 2*t],     0.f);
                float v1 = fmaxf(sstg[r * 132 + cb + 2*t + 1] + bias[nb0 + cb + 2*t + 1], 0.f);
                split2h(v0, v1, hh[t], mm[t]);
            }
            const size_t o = crow(gr) + nb0 + cb;
            *(uint4*)(Yh + o) = *(uint4*)hh;
            *(uint4*)(Ym + o) = *(uint4*)mm;
        }
    } else {
        const __half* Xh = g.Xh[z]; const __half* Xm = g.Xm[z];
        const int fbase = blockIdx.x * 64;
        const int fl0   = (tid & 1) * 32;
#pragma unroll
        for (int c8 = 0; c8 < 4; c8++) {
            const int fl = fl0 + c8 * 8;
            const int f  = fbase + fl;
            uint4 xh4 = *(const uint4*)(Xh + crow(gr) + f);
            uint4 xm4 = *(const uint4*)(Xm + crow(gr) + f);
            u32 hh[4], mm[4];
            float ov[8];
#pragma unroll
            for (int t = 0; t < 4; t++) {
                float2 xh2 = __half22float2(*(__half2*)&((u32*)&xh4)[t]);
                float2 xm2 = __half22float2(*(__half2*)&((u32*)&xm4)[t]);
                float x0 = xh2.x + xm2.x, x1 = xh2.y + xm2.y;
                float nl0 = sstg[r * 132 + fl + 2*t]       + bias[f + 2*t];
                float nl1 = sstg[r * 132 + fl + 2*t + 1]   + bias[f + 2*t + 1];
                float gt0 = sstg[r * 132 + 64 + fl + 2*t]     + bias[512 + f + 2*t];
                float gt1 = sstg[r * 132 + 64 + fl + 2*t + 1] + bias[512 + f + 2*t + 1];
                float s0 = 1.f / (1.f + __expf(-gt0));
                float s1 = 1.f / (1.f + __expf(-gt1));
                float o0 = s0 * x0 + (1.f - s0) * fmaxf(nl0, 0.f);
                float o1 = s1 * x1 + (1.f - s1) * fmaxf(nl1, 0.f);
                split2h(o0, o1, hh[t], mm[t]);
                ov[2*t] = o0; ov[2*t + 1] = o1;
            }
            const size_t yo = crow(gr) + f;
            *(uint4*)(Yh + yo) = *(uint4*)hh;
            *(uint4*)(Ym + yo) = *(uint4*)mm;
            if (MODE == 2) {
                float* outp = g.outp[z];
                *(float4*)(outp + (size_t)gr * 1024 + f)     = *(float4*)&ov[0];
                *(float4*)(outp + (size_t)gr * 1024 + f + 4) = *(float4*)&ov[4];
            }
        }
    }
}

// ================= prep kernels =================
__global__ void prep_convW(const float* __restrict__ Wf, const float* __restrict__ Wb,
                           __half* __restrict__ Of, __half* __restrict__ Ob) {
    // W: [3][2560][512] -> O: [3][512 n][2560 k], fp16
    int gid = blockIdx.x * blockDim.x + threadIdx.x;
    int zdir = blockIdx.y;
    const float* W = zdir ? Wb : Wf;
    __half* O = zdir ? Ob : Of;
    int w = gid >> 5;
    int lane = threadIdx.x & 31;
    int layer = w / (16 * 320); int rem = w % (16 * 320);
    int n = (rem / 320) * 32 + lane; int k0 = (rem % 320) * 8;
    const float* src = W + (size_t)layer * 2560 * 512 + (size_t)k0 * 512 + n;
    __half2 h2[4];
#pragma unroll
    for (int t = 0; t < 4; t++)
        h2[t] = __float22half2_rn(make_float2(src[(2*t) * 512], src[(2*t + 1) * 512]));
    size_t o = ((size_t)layer * 512 + n) * 2560 + k0;
    *(uint4*)(O + o) = *(uint4*)h2;
}

__global__ void prep_hwW(const float* __restrict__ Wf, const float* __restrict__ Wb,
                         __half* __restrict__ Of, __half* __restrict__ Ob) {
    // W: [6][512][1024] -> O: [6][1024 q][512 k], fp16
    // q: block fb covers cols [fb*128, fb*128+128): 0-63 nl, 64-127 gate of features fb*64..
    int gid = blockIdx.x * blockDim.x + threadIdx.x;
    int zdir = blockIdx.y;
    const float* W = zdir ? Wb : Wf;
    __half* O = zdir ? Ob : Of;
    int w = gid >> 5;
    int lane = threadIdx.x & 31;
    int lw = w / (32 * 64); int rem = w % (32 * 64);
    int np = (rem / 64) * 32 + lane; int k0 = (rem % 64) * 8;
    int f = (np < 512) ? np : (np - 512);
    int q = (f >> 6) * 128 + ((np < 512) ? (f & 63) : (64 + (f & 63)));
    const float* src = W + (size_t)lw * 512 * 1024 + (size_t)k0 * 1024 + np;
    __half2 h2[4];
#pragma unroll
    for (int t = 0; t < 4; t++)
        h2[t] = __float22half2_rn(make_float2(src[(2*t) * 1024], src[(2*t + 1) * 1024]));
    size_t o = ((size_t)lw * 1024 + q) * 512 + k0;
    *(uint4*)(O + o) = *(uint4*)h2;
}

__global__ void prep_act(const float* __restrict__ in,
                         __half* __restrict__ fh, __half* __restrict__ fm,
                         __half* __restrict__ bh, __half* __restrict__ bm) {
    int idx = blockIdx.x * 256 + threadIdx.x;
    int e = idx << 2;
    int r = e >> 9, h = e & 511;
    float4 v = *(const float4*)(in + e);
    u32 hw2[2], mw2[2];
    split2h(v.x, v.y, hw2[0], mw2[0]);
    split2h(v.z, v.w, hw2[1], mw2[1]);
    size_t o = crow(r) + h;
    *(uint2*)(fh + o) = *(uint2*)hw2; *(uint2*)(fm + o) = *(uint2*)mw2;
    *(uint2*)(bh + o) = *(uint2*)hw2; *(uint2*)(bm + o) = *(uint2*)mw2;
}

__global__ void prep_pads(const float* __restrict__ fp, const float* __restrict__ bp,
                          __half* __restrict__ fh, __half* __restrict__ fm,
                          __half* __restrict__ bh, __half* __restrict__ bm) {
    int idx = blockIdx.x * 256 + threadIdx.x;
    int e = idx << 2;
    int b = e >> 12; int rem = e & 4095; int p = rem >> 9; int h = rem & 511;
    const float* s = (p < 4) ? (fp + p * 512 + h) : (bp + (p - 4) * 512 + h);
    int row = (p < 4) ? (b * 520 + p) : (b * 520 + 516 + (p - 4));
    float4 v = *(const float4*)s;
    u32 hw2[2], mw2[2];
    split2h(v.x, v.y, hw2[0], mw2[0]);
    split2h(v.z, v.w, hw2[1], mw2[1]);
    size_t o = (size_t)row * 512 + h;
    *(uint2*)(fh + o) = *(uint2*)hw2; *(uint2*)(fm + o) = *(uint2*)mw2;
    *(uint2*)(bh + o) = *(uint2*)hw2; *(uint2*)(bm + o) = *(uint2*)mw2;
}

// ================= host =================
extern "C" void kernel_launch(void* const* d_in, const int* in_sizes, int n_in,
                              void* d_out, int out_size)
{
    const float* inputs   = (const float*)d_in[0];
    const float* fwd_pads = (const float*)d_in[2];
    const float* bwd_pads = (const float*)d_in[3];
    const float* fwd_W    = (const float*)d_in[4];
    const float* fwd_bi   = (const float*)d_in[5];
    const float* bwd_W    = (const float*)d_in[6];
    const float* bwd_bi   = (const float*)d_in[7];
    const float* fwd_hw_W = (const float*)d_in[8];
    const float* fwd_hw_b = (const float*)d_in[9];
    const float* bwd_hw_W = (const float*)d_in[10];
    const float* bwd_hw_b = (const float*)d_in[11];
    float* out = (float*)d_out;

    __half *pfB, *pbB, *cwB, *hwB;
    cudaGetSymbolAddress((void**)&pfB, g_pf);
    cudaGetSymbolAddress((void**)&pbB, g_pb);
    cudaGetSymbolAddress((void**)&cwB, g_cW);
    cudaGetSymbolAddress((void**)&hwB, g_hW);
    __half *pfh[2] = { pfB,       pfB + 2*(size_t)PSZ };
    __half *pfm[2] = { pfB + PSZ, pfB + 3*(size_t)PSZ };
    __half *pbh[2] = { pbB,       pbB + 2*(size_t)PSZ };
    __half *pbm[2] = { pbB + PSZ, pbB + 3*(size_t)PSZ };
    __half *cw[2]  = { cwB,       cwB + 3*(size_t)CWL };
    __half *hw[2]  = { hwB,       hwB + 6*(size_t)HWL };

    cudaFuncSetAttribute(mma_gemm<2560,0>, cudaFuncAttributeMaxDynamicSharedMemorySize, DSM);
    cudaFuncSetAttribute(mma_gemm<512,1>,  cudaFuncAttributeMaxDynamicSharedMemorySize, DSM);
    cudaFuncSetAttribute(mma_gemm<512,2>,  cudaFuncAttributeMaxDynamicSharedMemorySize, DSM);

    prep_convW<<<dim3(1920,2), 256>>>(fwd_W, bwd_W, cw[0], cw[1]);
    prep_hwW<<<dim3(1536,2), 256>>>(fwd_hw_W, bwd_hw_W, hw[0], hw[1]);
    prep_act<<<8192, 256>>>(inputs, pfh[0] + INTOFF, pfm[0] + INTOFF,
                                    pbh[0] + INTOFF, pbm[0] + INTOFF);

    int c = 0;
    for (int l = 0; l < 3; l++) {
        const int d = 1 - c;
        prep_pads<<<128, 256>>>(fwd_pads + (size_t)l * 2048, bwd_pads + (size_t)l * 2048,
                                pfh[c], pfm[c], pbh[c], pbm[c]);

        GemmArgs a{};

        // conv: buf[c] (padded) -> buf[d] interior, relu+bias
        a.Ah[0] = pfh[c];        a.Am[0] = pfm[c];
        a.Ah[1] = pbh[c] + 2048; a.Am[1] = pbm[c] + 2048;
        a.W[0] = cw[0] + (size_t)l*CWL;  a.W[1] = cw[1] + (size_t)l*CWL;
        a.bias[0] = fwd_bi + (size_t)l*512; a.bias[1] = bwd_bi + (size_t)l*512;
        a.Yh[0] = pfh[d] + INTOFF; a.Ym[0] = pfm[d] + INTOFF;
        a.Yh[1] = pbh[d] + INTOFF; a.Ym[1] = pbm[d] + INTOFF;
        mma_gemm<2560,0><<<dim3(4,128,2), 256, DSM>>>(a);

        // hw1: buf[d] -> buf[c]
        a.Ah[0] = pfh[d] + INTOFF; a.Am[0] = pfm[d] + INTOFF;
        a.Ah[1] = pbh[d] + INTOFF; a.Am[1] = pbm[d] + INTOFF;
        a.W[0] = hw[0] + (size_t)(l*2)*HWL; a.W[1] = hw[1] + (size_t)(l*2)*HWL;
        a.bias[0] = fwd_hw_b + (size_t)(l*2)*1024; a.bias[1] = bwd_hw_b + (size_t)(l*2)*1024;
        a.Xh[0] = pfh[d] + INTOFF; a.Xm[0] = pfm[d] + INTOFF;
        a.Xh[1] = pbh[d] + INTOFF; a.Xm[1] = pbm[d] + INTOFF;
        a.Yh[0] = pfh[c] + INTOFF; a.Ym[0] = pfm[c] + INTOFF;
        a.Yh[1] = pbh[c] + INTOFF; a.Ym[1] = pbm[c] + INTOFF;
        mma_gemm<512,1><<<dim3(8,128,2), 256, DSM>>>(a);

        // hw2: buf[c] -> buf[d], + fp32 output
        a.Ah[0] = pfh[c] + INTOFF; a.Am[0] = pfm[c] + INTOFF;
        a.Ah[1] = pbh[c] + INTOFF; a.Am[1] = pbm[c] + INTOFF;
        a.W[0] = hw[0] + (size_t)(l*2+1)*HWL; a.W[1] = hw[1] + (size_t)(l*2+1)*HWL;
        a.bias[0] = fwd_hw_b + (size_t)(l*2+1)*1024; a.bias[1] = bwd_hw_b + (size_t)(l*2+1)*1024;
        a.Xh[0] = pfh[c] + INTOFF; a.Xm[0] = pfm[c] + INTOFF;
        a.Xh[1] = pbh[c] + INTOFF; a.Xm[1] = pbm[c] + INTOFF;
        a.Yh[0] = pfh[d] + INTOFF; a.Ym[0] = pfm[d] + INTOFF;
        a.Yh[1] = pbh[d] + INTOFF; a.Ym[1] = pbm[d] + INTOFF;
        a.outp[0] = out + (size_t)l * MTr * 1024;
        a.outp[1] = out + (size_t)l * MTr * 1024 + 512;
        mma_gemm<512,2><<<dim3(8,128,2), 256, DSM>>>(a);

        c = d;
    }
}

// round 10
// speedup vs baseline: 3.7631x; 1.6132x over previous
#include <cuda_runtime.h>
#include <cuda_fp16.h>
#include <cstdint>

typedef unsigned int u32;
typedef unsigned long long u64;

#define Hd   512
#define SPd  520
#define MTr  16384
#define PSZ  (32*SPd*Hd)
#define INTOFF 2048
#define CWL  (512*2560)
#define HWL  (1024*512)

// ---------------- static device scratch ----------------
__device__ __half g_pf[2][PSZ];      // fwd padded activations (ping-pong), fp16
__device__ __half g_pb[2][PSZ];      // bwd
__device__ __half g_cW[2][3*CWL];    // conv weights [dir][layer][512 n][2560 k]
__device__ __half g_hW[2][6*HWL];    // hw weights   [dir][l*2+j][1024 q][512 k]

// ---------------- helpers ----------------
__device__ __forceinline__ u32 s2u(const void* p) {
    u32 a; asm("{ .reg .u64 t; cvta.to.shared.u64 t, %1; cvt.u32.u64 %0, t; }"
               : "=r"(a) : "l"(p)); return a;
}
__device__ __forceinline__ void cp16(u32 d, const void* s) {
    asm volatile("cp.async.cg.shared.global [%0], [%1], 16;" :: "r"(d), "l"(s) : "memory");
}
__device__ __forceinline__ void ldsm4(u32* r, u32 a) {
    asm volatile("ldmatrix.sync.aligned.m8n8.x4.shared.b16 {%0,%1,%2,%3}, [%4];"
                 : "=r"(r[0]), "=r"(r[1]), "=r"(r[2]), "=r"(r[3]) : "r"(a));
}
__device__ __forceinline__ void mma16816(float* d, const u32* a, const u32* b) {
    asm volatile("mma.sync.aligned.m16n8k16.row.col.f32.f16.f16.f32 "
                 "{%0,%1,%2,%3}, {%4,%5,%6,%7}, {%8,%9}, {%0,%1,%2,%3};"
                 : "+f"(d[0]), "+f"(d[1]), "+f"(d[2]), "+f"(d[3])
                 : "r"(a[0]), "r"(a[1]), "r"(a[2]), "r"(a[3]), "r"(b[0]), "r"(b[1]));
}

__device__ __forceinline__ size_t crow(int r) {
    return (size_t)(r + ((r >> 9) << 3)) * Hd;   // conv-mapped padded row
}
__device__ __forceinline__ u32 swz(int row, int ch) {   // 64B-row XOR swizzle
    return (u32)(row * 64 + ((ch ^ ((row >> 1) & 3)) << 4));
}

#define STAGE 16384            // A: 8KB + B: 8KB
#define NSTG  4
#define DSM   (128 + 128*132*4)   // 67.7KB staging bound (covers 64KB pipeline)

struct GemmArgs {
    const __half* A[2];
    const __half* W[2];  const float* bias[2];
    const __half* X[2];
    __half* Y[2];
    float*  outp[2];
};

// ================= single-pass fp16 HMMA GEMM + fused epilogue =================
// MODE 0: conv -> relu(D+bias), fp16 store to Y (conv-mapped)
// MODE 1: hw   -> gated combine with X (64-block nl/gate interleave), fp16 store
// MODE 2: hw   -> same + fp32 store to outp
template<int K, int MODE>
__global__ __launch_bounds__(256, 2)
void mma_gemm(GemmArgs g)
{
    constexpr int NC = K / 32;
    extern __shared__ char dsm[];
    const u32 base = (s2u(dsm) + 127) & ~127u;
    float* sstg = (float*)(dsm + (base - s2u(dsm)));   // UNION with pipeline stages

    const int z = blockIdx.z;
    const __half* __restrict__ A = g.A[z];
    const __half* __restrict__ W = g.W[z];
    const float*  __restrict__ bias = g.bias[z];

    const int tid  = threadIdx.x;
    const int lane = tid & 31;
    const int wid  = tid >> 5;
    const int wm   = (wid >> 2) * 64;
    const int wn   = (wid & 3) * 32;
    const int m0   = blockIdx.y << 7;
    const int nb0  = blockIdx.x << 7;

    // A: 512 16B transfers/stage (2/thread), B: 512 (2/thread)
    const __half* aSrc[2]; u32 aOff[2];
    const __half* bSrc[2]; u32 bOff[2];
#pragma unroll
    for (int it = 0; it < 2; it++) {
        int v = tid + it * 256;
        int row = v >> 2, ch = v & 3;
        aSrc[it] = A + crow(m0 + row) + ch * 8;
        aOff[it] = swz(row, ch);
        bSrc[it] = W + (size_t)(nb0 + row) * K + ch * 8;
        bOff[it] = 8192u + swz(row, ch);
    }

    auto load_chunk = [&](int c) {
        const u32 sb = base + (u32)((c & 3) * STAGE);
        const int kc = c * 32;
#pragma unroll
        for (int it = 0; it < 2; it++) cp16(sb + aOff[it], aSrc[it] + kc);
#pragma unroll
        for (int it = 0; it < 2; it++) cp16(sb + bOff[it], bSrc[it] + kc);
        asm volatile("cp.async.commit_group;" ::: "memory");
    };

    float acc[4][4][4];
#pragma unroll
    for (int i = 0; i < 4; i++)
#pragma unroll
        for (int j = 0; j < 4; j++)
#pragma unroll
            for (int q = 0; q < 4; q++) acc[i][j][q] = 0.f;

    load_chunk(0); load_chunk(1); load_chunk(2);

    const int ar = lane & 15;
    const int ac = lane >> 4;
    const int br = (lane & 7) + ((lane & 16) >> 1);
    const int bc = (lane >> 3) & 1;

    for (int c = 0; c < NC; c++) {
        asm volatile("cp.async.wait_group 2;" ::: "memory");
        __syncthreads();
        if (c + 3 < NC) load_chunk(c + 3);
        else            asm volatile("cp.async.commit_group;" ::: "memory");

        const u32 sb = base + (u32)((c & 3) * STAGE);
#pragma unroll
        for (int s = 0; s < 2; s++) {
            u32 bfb[8], afr[4][4];
            ldsm4(&bfb[0], sb + 8192 + swz(wn + br, 2 * s + bc));
            ldsm4(&bfb[4], sb + 8192 + swz(wn + 16 + br, 2 * s + bc));
#pragma unroll
            for (int i = 0; i < 4; i++)
                ldsm4(afr[i], sb + swz(wm + i * 16 + ar, 2 * s + ac));
#pragma unroll
            for (int i = 0; i < 4; i++)
#pragma unroll
                for (int j = 0; j < 4; j++)
                    mma16816(acc[i][j], afr[i], &bfb[j * 2]);
        }
    }

    // ---- stage accumulators to smem (pipeline smem now dead) ----
    __syncthreads();
#pragma unroll
    for (int i = 0; i < 4; i++)
#pragma unroll
        for (int j = 0; j < 4; j++) {
            int r0 = wm + i * 16 + (lane >> 2);
            int cc = wn + j * 8 + (lane & 3) * 2;
            *(float2*)&sstg[r0 * 132 + cc]       = make_float2(acc[i][j][0], acc[i][j][1]);
            *(float2*)&sstg[(r0 + 8) * 132 + cc] = make_float2(acc[i][j][2], acc[i][j][3]);
        }
    __syncthreads();

    // ---- fused, coalesced epilogue ----
    const int r  = tid >> 1;
    const int gr = m0 + r;
    __half* Y = g.Y[z];

    if (MODE == 0) {
        const int c0 = (tid & 1) * 64;
#pragma unroll
        for (int c8 = 0; c8 < 8; c8++) {
            const int cb = c0 + c8 * 8;
            __half2 hv[4];
#pragma unroll
            for (int t = 0; t < 4; t++) {
                float v0 = fmaxf(sstg[r * 132 + cb + 2*t]     + bias[nb0 + cb + 2*t],     0.f);
                float v1 = fmaxf(sstg[r * 132 + cb + 2*t + 1] + bias[nb0 + cb + 2*t + 1], 0.f);
                hv[t] = __float22half2_rn(make_float2(v0, v1));
            }
            *(uint4*)(Y + crow(gr) + nb0 + cb) = *(uint4*)hv;
        }
    } else {
        const __half* X = g.X[z];
        const int fbase = blockIdx.x * 64;
        const int fl0   = (tid & 1) * 32;
#pragma unroll
        for (int c8 = 0; c8 < 4; c8++) {
            const int fl = fl0 + c8 * 8;
            const int f  = fbase + fl;
            uint4 x4 = *(const uint4*)(X + crow(gr) + f);
            __half2 hv[4];
            float ov[8];
#pragma unroll
            for (int t = 0; t < 4; t++) {
                float2 x2 = __half22float2(*(__half2*)&((u32*)&x4)[t]);
                float nl0 = sstg[r * 132 + fl + 2*t]       + bias[f + 2*t];
                float nl1 = sstg[r * 132 + fl + 2*t + 1]   + bias[f + 2*t + 1];
                float gt0 = sstg[r * 132 + 64 + fl + 2*t]     + bias[512 + f + 2*t];
                float gt1 = sstg[r * 132 + 64 + fl + 2*t + 1] + bias[512 + f + 2*t + 1];
                float s0 = 1.f / (1.f + __expf(-gt0));
                float s1 = 1.f / (1.f + __expf(-gt1));
                float o0 = s0 * x2.x + (1.f - s0) * fmaxf(nl0, 0.f);
                float o1 = s1 * x2.y + (1.f - s1) * fmaxf(nl1, 0.f);
                hv[t] = __float22half2_rn(make_float2(o0, o1));
                ov[2*t] = o0; ov[2*t + 1] = o1;
            }
            *(uint4*)(Y + crow(gr) + f) = *(uint4*)hv;
            if (MODE == 2) {
                float* outp = g.outp[z];
                *(float4*)(outp + (size_t)gr * 1024 + f)     = *(float4*)&ov[0];
                *(float4*)(outp + (size_t)gr * 1024 + f + 4) = *(float4*)&ov[4];
            }
        }
    }
}

// ================= prep kernels =================
__global__ void prep_convW(const float* __restrict__ Wf, const float* __restrict__ Wb,
                           __half* __restrict__ Of, __half* __restrict__ Ob) {
    // W: [3][2560][512] -> O: [3][512 n][2560 k], fp16
    int gid = blockIdx.x * blockDim.x + threadIdx.x;
    const float* W = blockIdx.y ? Wb : Wf;
    __half* O = blockIdx.y ? Ob : Of;
    int w = gid >> 5;
    int lane = threadIdx.x & 31;
    int layer = w / (16 * 320); int rem = w % (16 * 320);
    int n = (rem / 320) * 32 + lane; int k0 = (rem % 320) * 8;
    const float* src = W + (size_t)layer * 2560 * 512 + (size_t)k0 * 512 + n;
    __half2 h2[4];
#pragma unroll
    for (int t = 0; t < 4; t++)
        h2[t] = __float22half2_rn(make_float2(src[(2*t) * 512], src[(2*t + 1) * 512]));
    size_t o = ((size_t)layer * 512 + n) * 2560 + k0;
    *(uint4*)(O + o) = *(uint4*)h2;
}

__global__ void prep_hwW(const float* __restrict__ Wf, const float* __restrict__ Wb,
                         __half* __restrict__ Of, __half* __restrict__ Ob) {
    // W: [6][512][1024] -> O: [6][1024 q][512 k], fp16
    // q: block fb covers cols [fb*128, fb*128+128): 0-63 nl, 64-127 gate of features fb*64..
    int gid = blockIdx.x * blockDim.x + threadIdx.x;
    const float* W = blockIdx.y ? Wb : Wf;
    __half* O = blockIdx.y ? Ob : Of;
    int w = gid >> 5;
    int lane = threadIdx.x & 31;
    int lw = w / (32 * 64); int rem = w % (32 * 64);
    int np = (rem / 64) * 32 + lane; int k0 = (rem % 64) * 8;
    int f = (np < 512) ? np : (np - 512);
    int q = (f >> 6) * 128 + ((np < 512) ? (f & 63) : (64 + (f & 63)));
    const float* src = W + (size_t)lw * 512 * 1024 + (size_t)k0 * 1024 + np;
    __half2 h2[4];
#pragma unroll
    for (int t = 0; t < 4; t++)
        h2[t] = __float22half2_rn(make_float2(src[(2*t) * 1024], src[(2*t + 1) * 1024]));
    size_t o = ((size_t)lw * 1024 + q) * 512 + k0;
    *(uint4*)(O + o) = *(uint4*)h2;
}

__global__ void prep_act(const float* __restrict__ in,
                         __half* __restrict__ fh, __half* __restrict__ bh) {
    int idx = blockIdx.x * 256 + threadIdx.x;
    int e = idx << 2;
    int r = e >> 9, h = e & 511;
    float4 v = *(const float4*)(in + e);
    __half2 h2[2];
    h2[0] = __float22half2_rn(make_float2(v.x, v.y));
    h2[1] = __float22half2_rn(make_float2(v.z, v.w));
    size_t o = crow(r) + h;
    *(uint2*)(fh + o) = *(uint2*)h2;
    *(uint2*)(bh + o) = *(uint2*)h2;
}

__global__ void prep_pads(const float* __restrict__ fp, const float* __restrict__ bp,
                          __half* __restrict__ fh, __half* __restrict__ bh) {
    int idx = blockIdx.x * 256 + threadIdx.x;
    int e = idx << 2;
    int b = e >> 12; int rem = e & 4095; int p = rem >> 9; int h = rem & 511;
    const float* s = (p < 4) ? (fp + p * 512 + h) : (bp + (p - 4) * 512 + h);
    int row = (p < 4) ? (b * 520 + p) : (b * 520 + 516 + (p - 4));
    float4 v = *(const float4*)s;
    __half2 h2[2];
    h2[0] = __float22half2_rn(make_float2(v.x, v.y));
    h2[1] = __float22half2_rn(make_float2(v.z, v.w));
    size_t o = (size_t)row * 512 + h;
    *(uint2*)(fh + o) = *(uint2*)h2;
    *(uint2*)(bh + o) = *(uint2*)h2;
}

// ================= host =================
extern "C" void kernel_launch(void* const* d_in, const int* in_sizes, int n_in,
                              void* d_out, int out_size)
{
    const float* inputs   = (const float*)d_in[0];
    const float* fwd_pads = (const float*)d_in[2];
    const float* bwd_pads = (const float*)d_in[3];
    const float* fwd_W    = (const float*)d_in[4];
    const float* fwd_bi   = (const float*)d_in[5];
    const float* bwd_W    = (const float*)d_in[6];
    const float* bwd_bi   = (const float*)d_in[7];
    const float* fwd_hw_W = (const float*)d_in[8];
    const float* fwd_hw_b = (const float*)d_in[9];
    const float* bwd_hw_W = (const float*)d_in[10];
    const float* bwd_hw_b = (const float*)d_in[11];
    float* out = (float*)d_out;

    __half *pfB, *pbB, *cwB, *hwB;
    cudaGetSymbolAddress((void**)&pfB, g_pf);
    cudaGetSymbolAddress((void**)&pbB, g_pb);
    cudaGetSymbolAddress((void**)&cwB, g_cW);
    cudaGetSymbolAddress((void**)&hwB, g_hW);
    __half *pf[2] = { pfB, pfB + (size_t)PSZ };
    __half *pb[2] = { pbB, pbB + (size_t)PSZ };
    __half *cw[2] = { cwB, cwB + 3*(size_t)CWL };
    __half *hw[2] = { hwB, hwB + 6*(size_t)HWL };

    cudaFuncSetAttribute(mma_gemm<2560,0>, cudaFuncAttributeMaxDynamicSharedMemorySize, DSM);
    cudaFuncSetAttribute(mma_gemm<512,1>,  cudaFuncAttributeMaxDynamicSharedMemorySize, DSM);
    cudaFuncSetAttribute(mma_gemm<512,2>,  cudaFuncAttributeMaxDynamicSharedMemorySize, DSM);

    prep_convW<<<dim3(1920,2), 256>>>(fwd_W, bwd_W, cw[0], cw[1]);
    prep_hwW<<<dim3(1536,2), 256>>>(fwd_hw_W, bwd_hw_W, hw[0], hw[1]);
    prep_act<<<8192, 256>>>(inputs, pf[0] + INTOFF, pb[0] + INTOFF);

    int c = 0;
    for (int l = 0; l < 3; l++) {
        const int d = 1 - c;
        prep_pads<<<128, 256>>>(fwd_pads + (size_t)l * 2048, bwd_pads + (size_t)l * 2048,
                                pf[c], pb[c]);

        GemmArgs a{};

        // conv: buf[c] (padded) -> buf[d] interior, relu+bias
        a.A[0] = pf[c];        a.A[1] = pb[c] + 2048;
        a.W[0] = cw[0] + (size_t)l*CWL;  a.W[1] = cw[1] + (size_t)l*CWL;
        a.bias[0] = fwd_bi + (size_t)l*512; a.bias[1] = bwd_bi + (size_t)l*512;
        a.Y[0] = pf[d] + INTOFF; a.Y[1] = pb[d] + INTOFF;
        mma_gemm<2560,0><<<dim3(4,128,2), 256, DSM>>>(a);

        // hw1: buf[d] -> buf[c]
        a.A[0] = pf[d] + INTOFF; a.A[1] = pb[d] + INTOFF;
        a.W[0] = hw[0] + (size_t)(l*2)*HWL; a.W[1] = hw[1] + (size_t)(l*2)*HWL;
        a.bias[0] = fwd_hw_b + (size_t)(l*2)*1024; a.bias[1] = bwd_hw_b + (size_t)(l*2)*1024;
        a.X[0] = pf[d] + INTOFF; a.X[1] = pb[d] + INTOFF;
        a.Y[0] = pf[c] + INTOFF; a.Y[1] = pb[c] + INTOFF;
        mma_gemm<512,1><<<dim3(8,128,2), 256, DSM>>>(a);

        // hw2: buf[c] -> buf[d], + fp32 output
        a.A[0] = pf[c] + INTOFF; a.A[1] = pb[c] + INTOFF;
        a.W[0] = hw[0] + (size_t)(l*2+1)*HWL; a.W[1] = hw[1] + (size_t)(l*2+1)*HWL;
        a.bias[0] = fwd_hw_b + (size_t)(l*2+1)*1024; a.bias[1] = bwd_hw_b + (size_t)(l*2+1)*1024;
        a.X[0] = pf[c] + INTOFF; a.X[1] = pb[c] + INTOFF;
        a.Y[0] = pf[d] + INTOFF; a.Y[1] = pb[d] + INTOFF;
        a.outp[0] = out + (size_t)l * MTr * 1024;
        a.outp[1] = out + (size_t)l * MTr * 1024 + 512;
        mma_gemm<512,2><<<dim3(8,128,2), 256, DSM>>>(a);

        c = d;
    }
}

// round 11
// speedup vs baseline: 3.8655x; 1.0272x over previous
#include <cuda_runtime.h>
#include <cuda_fp16.h>
#include <cstdint>

typedef unsigned int u32;
typedef unsigned long long u64;

#define Hd   512
#define SPd  520
#define MTr  16384
#define PSZ  (32*SPd*Hd)
#define INTOFF 2048
#define CWL  (512*2560)
#define HWL  (1024*512)

// ---------------- static device scratch ----------------
__device__ __half g_pf[2][PSZ];      // fwd padded activations (ping-pong), fp16
__device__ __half g_pb[2][PSZ];      // bwd
__device__ __half g_cW[2][3*CWL];    // conv weights [dir][layer][512 n][2560 k]
__device__ __half g_hW[2][6*HWL];    // hw weights   [dir][l*2+j][1024 q][512 k]

// scheduler state: tickets + completion counters [layer][phase][z][mtile]
__device__ int g_sync[3][2][2][128];
__device__ int g_tix[3];

// ---------------- helpers ----------------
__device__ __forceinline__ u32 s2u(const void* p) {
    u32 a; asm("{ .reg .u64 t; cvta.to.shared.u64 t, %1; cvt.u32.u64 %0, t; }"
               : "=r"(a) : "l"(p)); return a;
}
__device__ __forceinline__ void cp16(u32 d, const void* s) {
    asm volatile("cp.async.cg.shared.global [%0], [%1], 16;" :: "r"(d), "l"(s) : "memory");
}
__device__ __forceinline__ void ldsm4(u32* r, u32 a) {
    asm volatile("ldmatrix.sync.aligned.m8n8.x4.shared.b16 {%0,%1,%2,%3}, [%4];"
                 : "=r"(r[0]), "=r"(r[1]), "=r"(r[2]), "=r"(r[3]) : "r"(a));
}
__device__ __forceinline__ void mma16816(float* d, const u32* a, const u32* b) {
    asm volatile("mma.sync.aligned.m16n8k16.row.col.f32.f16.f16.f32 "
                 "{%0,%1,%2,%3}, {%4,%5,%6,%7}, {%8,%9}, {%0,%1,%2,%3};"
                 : "+f"(d[0]), "+f"(d[1]), "+f"(d[2]), "+f"(d[3])
                 : "r"(a[0]), "r"(a[1]), "r"(a[2]), "r"(a[3]), "r"(b[0]), "r"(b[1]));
}

__device__ __forceinline__ size_t crow(int r) {
    return (size_t)(r + ((r >> 9) << 3)) * Hd;   // conv-mapped padded row
}
__device__ __forceinline__ u32 swz(int row, int ch) {   // 64B-row XOR swizzle
    return (u32)(row * 64 + ((ch ^ ((row >> 1) & 3)) << 4));
}

#define STAGE 16384            // A: 8KB + B: 8KB
#define DSM   (128 + 128*132*4)   // 67.7KB staging bound (covers 64KB pipeline)

struct LayerArgs {
    int layer; int storeY2;
    const __half* Ac[2]; const __half* Wc[2]; const float* bc[2]; __half* Yc[2];
    const __half* W1[2]; const float* b1[2]; __half* Y1[2];
    const __half* W2[2]; const float* b2[2]; __half* Y2[2];
    float* outp[2];
};

// ============ fused per-layer kernel: conv + hw1 + hw2 via ticket queue ============
// tickets: [0,1024) conv (z=t&1, n=(t>>1)&3, m=t>>3)
//          [1024,3072) hw1  (z=u&1, n=(u>>1)&7, m=u>>4)
//          [3072,5120) hw2  (same decode)
// deps: hw1(m) needs conv cnt[z][m]==4 (and [m+1]==4 if m%4!=3, window WAR overlap)
//       hw2(m) needs hw1  cnt[z][m]==8
__global__ __launch_bounds__(256, 2)
void layer_kernel(LayerArgs a)
{
    extern __shared__ char dsm[];
    const u32 base = (s2u(dsm) + 127) & ~127u;
    float* sstg = (float*)(dsm + (base - s2u(dsm)));   // UNION with pipeline stages

    __shared__ int s_t;
    const int tid = threadIdx.x;
    if (tid == 0) s_t = atomicAdd(&g_tix[a.layer], 1);
    __syncthreads();
    const int t = s_t;

    int phase, m, n, z;
    if (t < 1024)      { phase = 0; z = t & 1; n = (t >> 1) & 3; m = t >> 3; }
    else if (t < 3072) { int u = t - 1024; phase = 1; z = u & 1; n = (u >> 1) & 7; m = u >> 4; }
    else               { int u = t - 3072; phase = 2; z = u & 1; n = (u >> 1) & 7; m = u >> 4; }

    int K;
    const __half *A, *W, *X = nullptr;
    const float* bias;
    __half* Y; float* op = nullptr;
    if (phase == 0)      { K = 2560; A = a.Ac[z]; W = a.Wc[z]; bias = a.bc[z]; Y = a.Yc[z]; }
    else if (phase == 1) { K = 512;  A = a.Yc[z]; X = A; W = a.W1[z]; bias = a.b1[z]; Y = a.Y1[z]; }
    else                 { K = 512;  A = a.Y1[z]; X = A; W = a.W2[z]; bias = a.b2[z];
                           Y = a.storeY2 ? a.Y2[z] : nullptr; op = a.outp[z]; }

    // ---- dependency wait (tid0 spins, broadcast via syncthreads) ----
    if (phase > 0) {
        if (tid == 0) {
            int* c0 = &g_sync[a.layer][phase - 1][z][m];
            const int tgt = (phase == 1) ? 4 : 8;
            while (atomicAdd(c0, 0) < tgt) __nanosleep(64);
            if (phase == 1 && (m & 3) != 3) {
                int* c1 = &g_sync[a.layer][0][z][m + 1];
                while (atomicAdd(c1, 0) < 4) __nanosleep(64);
            }
            __threadfence();
        }
        __syncthreads();
    }

    const int NC   = K >> 5;
    const int lane = tid & 31;
    const int wid  = tid >> 5;
    const int wm   = (wid >> 2) * 64;
    const int wn   = (wid & 3) * 32;
    const int m0   = m << 7;
    const int nb0  = n << 7;

    const __half* aSrc[2]; u32 aOff[2];
    const __half* bSrc[2]; u32 bOff[2];
#pragma unroll
    for (int it = 0; it < 2; it++) {
        int v = tid + it * 256;
        int row = v >> 2, ch = v & 3;
        aSrc[it] = A + crow(m0 + row) + ch * 8;
        aOff[it] = swz(row, ch);
        bSrc[it] = W + (size_t)(nb0 + row) * K + ch * 8;
        bOff[it] = 8192u + swz(row, ch);
    }

    auto load_chunk = [&](int c) {
        const u32 sb = base + (u32)((c & 3) * STAGE);
        const int kc = c * 32;
#pragma unroll
        for (int it = 0; it < 2; it++) cp16(sb + aOff[it], aSrc[it] + kc);
#pragma unroll
        for (int it = 0; it < 2; it++) cp16(sb + bOff[it], bSrc[it] + kc);
        asm volatile("cp.async.commit_group;" ::: "memory");
    };

    float acc[4][4][4];
#pragma unroll
    for (int i = 0; i < 4; i++)
#pragma unroll
        for (int j = 0; j < 4; j++)
#pragma unroll
            for (int q = 0; q < 4; q++) acc[i][j][q] = 0.f;

    load_chunk(0); load_chunk(1); load_chunk(2);

    const int ar = lane & 15;
    const int ac = lane >> 4;
    const int br = (lane & 7) + ((lane & 16) >> 1);
    const int bc = (lane >> 3) & 1;

    for (int c = 0; c < NC; c++) {
        asm volatile("cp.async.wait_group 2;" ::: "memory");
        __syncthreads();
        if (c + 3 < NC) load_chunk(c + 3);
        else            asm volatile("cp.async.commit_group;" ::: "memory");

        const u32 sb = base + (u32)((c & 3) * STAGE);
#pragma unroll
        for (int s = 0; s < 2; s++) {
            u32 bfb[8], afr[4][4];
            ldsm4(&bfb[0], sb + 8192 + swz(wn + br, 2 * s + bc));
            ldsm4(&bfb[4], sb + 8192 + swz(wn + 16 + br, 2 * s + bc));
#pragma unroll
            for (int i = 0; i < 4; i++)
                ldsm4(afr[i], sb + swz(wm + i * 16 + ar, 2 * s + ac));
#pragma unroll
            for (int i = 0; i < 4; i++)
#pragma unroll
                for (int j = 0; j < 4; j++)
                    mma16816(acc[i][j], afr[i], &bfb[j * 2]);
        }
    }

    // ---- stage accumulators to smem (pipeline smem now dead) ----
    __syncthreads();
#pragma unroll
    for (int i = 0; i < 4; i++)
#pragma unroll
        for (int j = 0; j < 4; j++) {
            int r0 = wm + i * 16 + (lane >> 2);
            int cc = wn + j * 8 + (lane & 3) * 2;
            *(float2*)&sstg[r0 * 132 + cc]       = make_float2(acc[i][j][0], acc[i][j][1]);
            *(float2*)&sstg[(r0 + 8) * 132 + cc] = make_float2(acc[i][j][2], acc[i][j][3]);
        }
    __syncthreads();

    // ---- fused, coalesced epilogue ----
    const int r  = tid >> 1;
    const int gr = m0 + r;

    if (phase == 0) {
        const int c0 = (tid & 1) * 64;
#pragma unroll
        for (int c8 = 0; c8 < 8; c8++) {
            const int cb = c0 + c8 * 8;
            __half2 hv[4];
#pragma unroll
            for (int tt = 0; tt < 4; tt++) {
                float v0 = fmaxf(sstg[r * 132 + cb + 2*tt]     + bias[nb0 + cb + 2*tt],     0.f);
                float v1 = fmaxf(sstg[r * 132 + cb + 2*tt + 1] + bias[nb0 + cb + 2*tt + 1], 0.f);
                hv[tt] = __float22half2_rn(make_float2(v0, v1));
            }
            *(uint4*)(Y + crow(gr) + nb0 + cb) = *(uint4*)hv;
        }
    } else {
        const int fbase = n * 64;
        const int fl0   = (tid & 1) * 32;
#pragma unroll
        for (int c8 = 0; c8 < 4; c8++) {
            const int fl = fl0 + c8 * 8;
            const int f  = fbase + fl;
            uint4 x4 = *(const uint4*)(X + crow(gr) + f);
            __half2 hv[4];
            float ov[8];
#pragma unroll
            for (int tt = 0; tt < 4; tt++) {
                float2 x2 = __half22float2(*(__half2*)&((u32*)&x4)[tt]);
                float nl0 = sstg[r * 132 + fl + 2*tt]       + bias[f + 2*tt];
                float nl1 = sstg[r * 132 + fl + 2*tt + 1]   + bias[f + 2*tt + 1];
                float gt0 = sstg[r * 132 + 64 + fl + 2*tt]     + bias[512 + f + 2*tt];
                float gt1 = sstg[r * 132 + 64 + fl + 2*tt + 1] + bias[512 + f + 2*tt + 1];
                float s0 = 1.f / (1.f + __expf(-gt0));
                float s1 = 1.f / (1.f + __expf(-gt1));
                float o0 = s0 * x2.x + (1.f - s0) * fmaxf(nl0, 0.f);
                float o1 = s1 * x2.y + (1.f - s1) * fmaxf(nl1, 0.f);
                hv[tt] = __float22half2_rn(make_float2(o0, o1));
                ov[2*tt] = o0; ov[2*tt + 1] = o1;
            }
            if (Y) *(uint4*)(Y + crow(gr) + f) = *(uint4*)hv;
            if (op) {
                *(float4*)(op + (size_t)gr * 1024 + f)     = *(float4*)&ov[0];
                *(float4*)(op + (size_t)gr * 1024 + f + 4) = *(float4*)&ov[4];
            }
        }
    }

    // ---- publish completion ----
    __threadfence();
    __syncthreads();
    if (tid == 0 && phase < 2) atomicAdd(&g_sync[a.layer][phase][z][m], 1);
}

// ================= prep kernels =================
__global__ void zero_sync() {
    int i = blockIdx.x * 256 + threadIdx.x;
    if (i < 3 * 2 * 2 * 128) ((int*)g_sync)[i] = 0;
    if (i < 3) g_tix[i] = 0;
}

__global__ void prep_convW(const float* __restrict__ Wf, const float* __restrict__ Wb,
                           __half* __restrict__ Of, __half* __restrict__ Ob) {
    int gid = blockIdx.x * blockDim.x + threadIdx.x;
    const float* W = blockIdx.y ? Wb : Wf;
    __half* O = blockIdx.y ? Ob : Of;
    int w = gid >> 5;
    int lane = threadIdx.x & 31;
    int layer = w / (16 * 320); int rem = w % (16 * 320);
    int n = (rem / 320) * 32 + lane; int k0 = (rem % 320) * 8;
    const float* src = W + (size_t)layer * 2560 * 512 + (size_t)k0 * 512 + n;
    __half2 h2[4];
#pragma unroll
    for (int t = 0; t < 4; t++)
        h2[t] = __float22half2_rn(make_float2(src[(2*t) * 512], src[(2*t + 1) * 512]));
    size_t o = ((size_t)layer * 512 + n) * 2560 + k0;
    *(uint4*)(O + o) = *(uint4*)h2;
}

__global__ void prep_hwW(const float* __restrict__ Wf, const float* __restrict__ Wb,
                         __half* __restrict__ Of, __half* __restrict__ Ob) {
    int gid = blockIdx.x * blockDim.x + threadIdx.x;
    const float* W = blockIdx.y ? Wb : Wf;
    __half* O = blockIdx.y ? Ob : Of;
    int w = gid >> 5;
    int lane = threadIdx.x & 31;
    int lw = w / (32 * 64); int rem = w % (32 * 64);
    int np = (rem / 64) * 32 + lane; int k0 = (rem % 64) * 8;
    int f = (np < 512) ? np : (np - 512);
    int q = (f >> 6) * 128 + ((np < 512) ? (f & 63) : (64 + (f & 63)));
    const float* src = W + (size_t)lw * 512 * 1024 + (size_t)k0 * 1024 + np;
    __half2 h2[4];
#pragma unroll
    for (int t = 0; t < 4; t++)
        h2[t] = __float22half2_rn(make_float2(src[(2*t) * 1024], src[(2*t + 1) * 1024]));
    size_t o = ((size_t)lw * 1024 + q) * 512 + k0;
    *(uint4*)(O + o) = *(uint4*)h2;
}

__global__ void prep_act(const float* __restrict__ in,
                         __half* __restrict__ fh, __half* __restrict__ bh) {
    int idx = blockIdx.x * 256 + threadIdx.x;
    int e = idx << 2;
    int r = e >> 9, h = e & 511;
    float4 v = *(const float4*)(in + e);
    __half2 h2[2];
    h2[0] = __float22half2_rn(make_float2(v.x, v.y));
    h2[1] = __float22half2_rn(make_float2(v.z, v.w));
    size_t o = crow(r) + h;
    *(uint2*)(fh + o) = *(uint2*)h2;
    *(uint2*)(bh + o) = *(uint2*)h2;
}

__global__ void prep_pads(const float* __restrict__ fp, const float* __restrict__ bp,
                          __half* __restrict__ fh, __half* __restrict__ bh) {
    int idx = blockIdx.x * 256 + threadIdx.x;
    int e = idx << 2;
    int b = e >> 12; int rem = e & 4095; int p = rem >> 9; int h = rem & 511;
    const float* s = (p < 4) ? (fp + p * 512 + h) : (bp + (p - 4) * 512 + h);
    int row = (p < 4) ? (b * 520 + p) : (b * 520 + 516 + (p - 4));
    float4 v = *(const float4*)s;
    __half2 h2[2];
    h2[0] = __float22half2_rn(make_float2(v.x, v.y));
    h2[1] = __float22half2_rn(make_float2(v.z, v.w));
    size_t o = (size_t)row * 512 + h;
    *(uint2*)(fh + o) = *(uint2*)h2;
    *(uint2*)(bh + o) = *(uint2*)h2;
}

// ================= host =================
extern "C" void kernel_launch(void* const* d_in, const int* in_sizes, int n_in,
                              void* d_out, int out_size)
{
    const float* inputs   = (const float*)d_in[0];
    const float* fwd_pads = (const float*)d_in[2];
    const float* bwd_pads = (const float*)d_in[3];
    const float* fwd_W    = (const float*)d_in[4];
    const float* fwd_bi   = (const float*)d_in[5];
    const float* bwd_W    = (const float*)d_in[6];
    const float* bwd_bi   = (const float*)d_in[7];
    const float* fwd_hw_W = (const float*)d_in[8];
    const float* fwd_hw_b = (const float*)d_in[9];
    const float* bwd_hw_W = (const float*)d_in[10];
    const float* bwd_hw_b = (const float*)d_in[11];
    float* out = (float*)d_out;

    __half *pfB, *pbB, *cwB, *hwB;
    cudaGetSymbolAddress((void**)&pfB, g_pf);
    cudaGetSymbolAddress((void**)&pbB, g_pb);
    cudaGetSymbolAddress((void**)&cwB, g_cW);
    cudaGetSymbolAddress((void**)&hwB, g_hW);
    __half *pf[2] = { pfB, pfB + (size_t)PSZ };
    __half *pb[2] = { pbB, pbB + (size_t)PSZ };
    __half *cw[2] = { cwB, cwB + 3*(size_t)CWL };
    __half *hw[2] = { hwB, hwB + 6*(size_t)HWL };

    cudaFuncSetAttribute(layer_kernel, cudaFuncAttributeMaxDynamicSharedMemorySize, DSM);

    zero_sync<<<6, 256>>>();
    prep_convW<<<dim3(1920,2), 256>>>(fwd_W, bwd_W, cw[0], cw[1]);
    prep_hwW<<<dim3(1536,2), 256>>>(fwd_hw_W, bwd_hw_W, hw[0], hw[1]);
    prep_act<<<8192, 256>>>(inputs, pf[0] + INTOFF, pb[0] + INTOFF);

    int c = 0;
    for (int l = 0; l < 3; l++) {
        const int d = 1 - c;
        prep_pads<<<128, 256>>>(fwd_pads + (size_t)l * 2048, bwd_pads + (size_t)l * 2048,
                                pf[c], pb[c]);

        LayerArgs a{};
        a.layer = l;
        a.storeY2 = (l < 2) ? 1 : 0;
        // conv: buf[c] (padded) -> buf[d] interior
        a.Ac[0] = pf[c];        a.Ac[1] = pb[c] + 2048;
        a.Wc[0] = cw[0] + (size_t)l*CWL;  a.Wc[1] = cw[1] + (size_t)l*CWL;
        a.bc[0] = fwd_bi + (size_t)l*512; a.bc[1] = bwd_bi + (size_t)l*512;
        a.Yc[0] = pf[d] + INTOFF; a.Yc[1] = pb[d] + INTOFF;
        // hw1: buf[d] -> buf[c]
        a.W1[0] = hw[0] + (size_t)(l*2)*HWL; a.W1[1] = hw[1] + (size_t)(l*2)*HWL;
        a.b1[0] = fwd_hw_b + (size_t)(l*2)*1024; a.b1[1] = bwd_hw_b + (size_t)(l*2)*1024;
        a.Y1[0] = pf[c] + INTOFF; a.Y1[1] = pb[c] + INTOFF;
        // hw2: buf[c] -> buf[d] (+ fp32 out)
        a.W2[0] = hw[0] + (size_t)(l*2+1)*HWL; a.W2[1] = hw[1] + (size_t)(l*2+1)*HWL;
        a.b2[0] = fwd_hw_b + (size_t)(l*2+1)*1024; a.b2[1] = bwd_hw_b + (size_t)(l*2+1)*1024;
        a.Y2[0] = pf[d] + INTOFF; a.Y2[1] = pb[d] + INTOFF;
        a.outp[0] = out + (size_t)l * MTr * 1024;
        a.outp[1] = out + (size_t)l * MTr * 1024 + 512;

        layer_kernel<<<5120, 256, DSM>>>(a);

        c = d;
    }
}

// round 12
// speedup vs baseline: 3.8761x; 1.0027x over previous
#include <cuda_runtime.h>
#include <cuda_fp16.h>
#include <cstdint>

typedef unsigned int u32;
typedef unsigned long long u64;

#define Hd   512
#define SPd  520
#define MTr  16384
#define PSZ  (32*SPd*Hd)
#define INTOFF 2048
#define CWL  (512*2560)
#define HWL  (1024*512)

// ---------------- static device scratch ----------------
__device__ __half g_P[2][3][PSZ];    // conv inputs per [dir][layer], padded, pads prefilled
__device__ __half g_T[2][PSZ];       // conv output / hw1 input   (interior-only use)
__device__ __half g_U[2][PSZ];       // hw1 output / hw2 input
__device__ __half g_cW[2][3*CWL];    // conv weights [dir][layer][512 n][2560 k]
__device__ __half g_hW[2][6*HWL];    // hw weights   [dir][l*2+j][1024 q][512 k]

// scheduler: completion counters [layer][phase][z][mtile] + global ticket
__device__ int g_sync[3][3][2][128];
__device__ int g_tix;

// ---------------- helpers ----------------
__device__ __forceinline__ u32 s2u(const void* p) {
    u32 a; asm("{ .reg .u64 t; cvta.to.shared.u64 t, %1; cvt.u32.u64 %0, t; }"
               : "=r"(a) : "l"(p)); return a;
}
__device__ __forceinline__ void cp16(u32 d, const void* s) {
    asm volatile("cp.async.cg.shared.global [%0], [%1], 16;" :: "r"(d), "l"(s) : "memory");
}
__device__ __forceinline__ void ldsm4(u32* r, u32 a) {
    asm volatile("ldmatrix.sync.aligned.m8n8.x4.shared.b16 {%0,%1,%2,%3}, [%4];"
                 : "=r"(r[0]), "=r"(r[1]), "=r"(r[2]), "=r"(r[3]) : "r"(a));
}
__device__ __forceinline__ void mma16816(float* d, const u32* a, const u32* b) {
    asm volatile("mma.sync.aligned.m16n8k16.row.col.f32.f16.f16.f32 "
                 "{%0,%1,%2,%3}, {%4,%5,%6,%7}, {%8,%9}, {%0,%1,%2,%3};"
                 : "+f"(d[0]), "+f"(d[1]), "+f"(d[2]), "+f"(d[3])
                 : "r"(a[0]), "r"(a[1]), "r"(a[2]), "r"(a[3]), "r"(b[0]), "r"(b[1]));
}
__device__ __forceinline__ size_t crow(int r) {
    return (size_t)(r + ((r >> 9) << 3)) * Hd;   // conv-mapped padded row
}
__device__ __forceinline__ u32 swz(int row, int ch) {   // 64B-row XOR swizzle
    return (u32)(row * 64 + ((ch ^ ((row >> 1) & 3)) << 4));
}
__device__ __forceinline__ void dwait(int* c, int tgt) {
    while (atomicAdd(c, 0) < tgt) __nanosleep(64);
}

#define STAGE 16384            // A: 8KB + B: 8KB
#define DSM   (128 + 128*132*4)   // 67.7KB staging bound (covers 64KB pipeline)

struct Args {
    const float *bc_f, *bc_b;    // conv biases [3][512]
    const float *bh_f, *bh_b;    // hw biases   [6][1024]
    float* out;
};

// ============ fully-fused 3-layer kernel via global ticket queue ============
// ticket t: layer = t/5120, u = t%5120
//   u in [0,1024):    conv  z=u&1, n=(u>>1)&3, m=u>>3
//   u in [1024,3072): hw1   z=v&1, n=(v>>1)&7, m=v>>4   (v=u-1024)
//   u in [3072,5120): hw2   (v=u-3072, same decode)
// deps (all strictly older tickets -> deadlock-free by monotone draw order):
//   conv(l>=1,z,m): hw2(l-1)[z][m]==8; fwd also [m-1]==8 (if m%4!=0),
//                   bwd also [m+1]==8 (if m%4!=3)      (4-row K-window)
//   hw1(l,z,m): conv(l)[z][m]==4
//   hw2(l,z,m): hw1(l)[z][m]==8
__global__ __launch_bounds__(256, 2)
void fused_kernel(Args a)
{
    extern __shared__ char dsm[];
    const u32 base = (s2u(dsm) + 127) & ~127u;
    float* sstg = (float*)(dsm + (base - s2u(dsm)));   // UNION with pipeline stages

    __shared__ int s_t;
    const int tid = threadIdx.x;
    if (tid == 0) s_t = atomicAdd(&g_tix, 1);
    __syncthreads();
    const int t = s_t;

    const int layer = t / 5120;
    const int u = t - layer * 5120;
    int phase, m, n, z;
    if (u < 1024)      { phase = 0; z = u & 1; n = (u >> 1) & 3; m = u >> 3; }
    else if (u < 3072) { int v = u - 1024; phase = 1; z = v & 1; n = (v >> 1) & 7; m = v >> 4; }
    else               { int v = u - 3072; phase = 2; z = v & 1; n = (v >> 1) & 7; m = v >> 4; }

    int K;
    const __half *A, *W, *X = nullptr;
    const float* bias;
    __half* Y = nullptr; float* op = nullptr;
    if (phase == 0) {
        K = 2560;
        A = &g_P[z][layer][0] + (z ? 2048 : 0);      // fwd window off 0, bwd off W rows
        W = &g_cW[z][(size_t)layer * CWL];
        bias = (z ? a.bc_b : a.bc_f) + layer * 512;
        Y = &g_T[z][INTOFF];
    } else if (phase == 1) {
        K = 512;
        A = X = &g_T[z][INTOFF];
        W = &g_hW[z][(size_t)(layer * 2) * HWL];
        bias = (z ? a.bh_b : a.bh_f) + (size_t)(layer * 2) * 1024;
        Y = &g_U[z][INTOFF];
    } else {
        K = 512;
        A = X = &g_U[z][INTOFF];
        W = &g_hW[z][(size_t)(layer * 2 + 1) * HWL];
        bias = (z ? a.bh_b : a.bh_f) + (size_t)(layer * 2 + 1) * 1024;
        Y = (layer < 2) ? &g_P[z][layer + 1][INTOFF] : nullptr;
        op = a.out + (size_t)layer * MTr * 1024 + z * 512;
    }

    // ---- dependency wait (tid0 spins, broadcast via syncthreads) ----
    if (tid == 0) {
        if (phase == 0) {
            if (layer > 0) {
                dwait(&g_sync[layer - 1][2][z][m], 8);
                if (z == 0) { if ((m & 3) != 0) dwait(&g_sync[layer - 1][2][0][m - 1], 8); }
                else        { if ((m & 3) != 3) dwait(&g_sync[layer - 1][2][1][m + 1], 8); }
            }
        } else if (phase == 1) {
            dwait(&g_sync[layer][0][z][m], 4);
        } else {
            dwait(&g_sync[layer][1][z][m], 8);
        }
        __threadfence();
    }
    __syncthreads();

    const int NC   = K >> 5;
    const int lane = tid & 31;
    const int wid  = tid >> 5;
    const int wm   = (wid >> 2) * 64;
    const int wn   = (wid & 3) * 32;
    const int m0   = m << 7;
    const int nb0  = n << 7;

    const __half* aSrc[2]; u32 aOff[2];
    const __half* bSrc[2]; u32 bOff[2];
#pragma unroll
    for (int it = 0; it < 2; it++) {
        int v = tid + it * 256;
        int row = v >> 2, ch = v & 3;
        aSrc[it] = A + crow(m0 + row) + ch * 8;
        aOff[it] = swz(row, ch);
        bSrc[it] = W + (size_t)(nb0 + row) * K + ch * 8;
        bOff[it] = 8192u + swz(row, ch);
    }

    auto load_chunk = [&](int c) {
        const u32 sb = base + (u32)((c & 3) * STAGE);
        const int kc = c * 32;
#pragma unroll
        for (int it = 0; it < 2; it++) cp16(sb + aOff[it], aSrc[it] + kc);
#pragma unroll
        for (int it = 0; it < 2; it++) cp16(sb + bOff[it], bSrc[it] + kc);
        asm volatile("cp.async.commit_group;" ::: "memory");
    };

    float acc[4][4][4];
#pragma unroll
    for (int i = 0; i < 4; i++)
#pragma unroll
        for (int j = 0; j < 4; j++)
#pragma unroll
            for (int q = 0; q < 4; q++) acc[i][j][q] = 0.f;

    load_chunk(0); load_chunk(1); load_chunk(2);

    const int ar = lane & 15;
    const int ac = lane >> 4;
    const int br = (lane & 7) + ((lane & 16) >> 1);
    const int bc = (lane >> 3) & 1;

    for (int c = 0; c < NC; c++) {
        asm volatile("cp.async.wait_group 2;" ::: "memory");
        __syncthreads();
        if (c + 3 < NC) load_chunk(c + 3);
        else            asm volatile("cp.async.commit_group;" ::: "memory");

        const u32 sb = base + (u32)((c & 3) * STAGE);
#pragma unroll
        for (int s = 0; s < 2; s++) {
            u32 bfb[8], afr[4][4];
            ldsm4(&bfb[0], sb + 8192 + swz(wn + br, 2 * s + bc));
            ldsm4(&bfb[4], sb + 8192 + swz(wn + 16 + br, 2 * s + bc));
#pragma unroll
            for (int i = 0; i < 4; i++)
                ldsm4(afr[i], sb + swz(wm + i * 16 + ar, 2 * s + ac));
#pragma unroll
            for (int i = 0; i < 4; i++)
#pragma unroll
                for (int j = 0; j < 4; j++)
                    mma16816(acc[i][j], afr[i], &bfb[j * 2]);
        }
    }

    // ---- stage accumulators to smem (pipeline smem now dead) ----
    __syncthreads();
#pragma unroll
    for (int i = 0; i < 4; i++)
#pragma unroll
        for (int j = 0; j < 4; j++) {
            int r0 = wm + i * 16 + (lane >> 2);
            int cc = wn + j * 8 + (lane & 3) * 2;
            *(float2*)&sstg[r0 * 132 + cc]       = make_float2(acc[i][j][0], acc[i][j][1]);
            *(float2*)&sstg[(r0 + 8) * 132 + cc] = make_float2(acc[i][j][2], acc[i][j][3]);
        }
    __syncthreads();

    // ---- fused, coalesced epilogue ----
    const int r  = tid >> 1;
    const int gr = m0 + r;

    if (phase == 0) {
        const int c0 = (tid & 1) * 64;
#pragma unroll
        for (int c8 = 0; c8 < 8; c8++) {
            const int cb = c0 + c8 * 8;
            __half2 hv[4];
#pragma unroll
            for (int tt = 0; tt < 4; tt++) {
                float v0 = fmaxf(sstg[r * 132 + cb + 2*tt]     + bias[nb0 + cb + 2*tt],     0.f);
                float v1 = fmaxf(sstg[r * 132 + cb + 2*tt + 1] + bias[nb0 + cb + 2*tt + 1], 0.f);
                hv[tt] = __float22half2_rn(make_float2(v0, v1));
            }
            *(uint4*)(Y + crow(gr) + nb0 + cb) = *(uint4*)hv;
        }
    } else {
        const int fbase = n * 64;
        const int fl0   = (tid & 1) * 32;
#pragma unroll
        for (int c8 = 0; c8 < 4; c8++) {
            const int fl = fl0 + c8 * 8;
            const int f  = fbase + fl;
            uint4 x4 = *(const uint4*)(X + crow(gr) + f);
            __half2 hv[4];
            float ov[8];
#pragma unroll
            for (int tt = 0; tt < 4; tt++) {
                float2 x2 = __half22float2(*(__half2*)&((u32*)&x4)[tt]);
                float nl0 = sstg[r * 132 + fl + 2*tt]       + bias[f + 2*tt];
                float nl1 = sstg[r * 132 + fl + 2*tt + 1]   + bias[f + 2*tt + 1];
                float gt0 = sstg[r * 132 + 64 + fl + 2*tt]     + bias[512 + f + 2*tt];
                float gt1 = sstg[r * 132 + 64 + fl + 2*tt + 1] + bias[512 + f + 2*tt + 1];
                float s0 = 1.f / (1.f + __expf(-gt0));
                float s1 = 1.f / (1.f + __expf(-gt1));
                float o0 = s0 * x2.x + (1.f - s0) * fmaxf(nl0, 0.f);
                float o1 = s1 * x2.y + (1.f - s1) * fmaxf(nl1, 0.f);
                hv[tt] = __float22half2_rn(make_float2(o0, o1));
                ov[2*tt] = o0; ov[2*tt + 1] = o1;
            }
            if (Y) *(uint4*)(Y + crow(gr) + f) = *(uint4*)hv;
            if (op) {
                *(float4*)(op + (size_t)gr * 1024 + f)     = *(float4*)&ov[0];
                *(float4*)(op + (size_t)gr * 1024 + f + 4) = *(float4*)&ov[4];
            }
        }
    }

    // ---- publish completion ----
    __threadfence();
    __syncthreads();
    if (tid == 0) atomicAdd(&g_sync[layer][phase][z][m], 1);
}

// ================= prep kernels =================
__global__ void zero_sync() {
    int i = blockIdx.x * 256 + threadIdx.x;
    if (i < 3 * 3 * 2 * 128) ((int*)g_sync)[i] = 0;
    if (i == 0) g_tix = 0;
}

__global__ void prep_convW(const float* __restrict__ Wf, const float* __restrict__ Wb) {
    int gid = blockIdx.x * blockDim.x + threadIdx.x;
    const float* W = blockIdx.y ? Wb : Wf;
    __half* O = &g_cW[blockIdx.y][0];
    int w = gid >> 5;
    int lane = threadIdx.x & 31;
    int layer = w / (16 * 320); int rem = w % (16 * 320);
    int n = (rem / 320) * 32 + lane; int k0 = (rem % 320) * 8;
    const float* src = W + (size_t)layer * 2560 * 512 + (size_t)k0 * 512 + n;
    __half2 h2[4];
#pragma unroll
    for (int t = 0; t < 4; t++)
        h2[t] = __float22half2_rn(make_float2(src[(2*t) * 512], src[(2*t + 1) * 512]));
    size_t o = ((size_t)layer * 512 + n) * 2560 + k0;
    *(uint4*)(O + o) = *(uint4*)h2;
}

__global__ void prep_hwW(const float* __restrict__ Wf, const float* __restrict__ Wb) {
    int gid = blockIdx.x * blockDim.x + threadIdx.x;
    const float* W = blockIdx.y ? Wb : Wf;
    __half* O = &g_hW[blockIdx.y][0];
    int w = gid >> 5;
    int lane = threadIdx.x & 31;
    int lw = w / (32 * 64); int rem = w % (32 * 64);
    int np = (rem / 64) * 32 + lane; int k0 = (rem % 64) * 8;
    int f = (np < 512) ? np : (np - 512);
    int q = (f >> 6) * 128 + ((np < 512) ? (f & 63) : (64 + (f & 63)));
    const float* src = W + (size_t)lw * 512 * 1024 + (size_t)k0 * 1024 + np;
    __half2 h2[4];
#pragma unroll
    for (int t = 0; t < 4; t++)
        h2[t] = __float22half2_rn(make_float2(src[(2*t) * 1024], src[(2*t + 1) * 1024]));
    size_t o = ((size_t)lw * 1024 + q) * 512 + k0;
    *(uint4*)(O + o) = *(uint4*)h2;
}

__global__ void prep_act(const float* __restrict__ in) {
    int idx = blockIdx.x * 256 + threadIdx.x;
    int e = idx << 2;
    int r = e >> 9, h = e & 511;
    float4 v = *(const float4*)(in + e);
    __half2 h2[2];
    h2[0] = __float22half2_rn(make_float2(v.x, v.y));
    h2[1] = __float22half2_rn(make_float2(v.z, v.w));
    size_t o = crow(r) + h + INTOFF;
    *(uint2*)(&g_P[0][0][0] + o) = *(uint2*)h2;
    *(uint2*)(&g_P[1][0][0] + o) = *(uint2*)h2;
}

__global__ void prep_pads(const float* __restrict__ fp, const float* __restrict__ bp) {
    // blockIdx.y = layer; fill pad rows of g_P[0][l] and g_P[1][l]
    int l = blockIdx.y;
    int idx = blockIdx.x * 256 + threadIdx.x;
    int e = idx << 2;
    int b = e >> 12; int rem = e & 4095; int p = rem >> 9; int h = rem & 511;
    const float* s = (p < 4) ? (fp + (size_t)l * 2048 + p * 512 + h)
                             : (bp + (size_t)l * 2048 + (p - 4) * 512 + h);
    int row = (p < 4) ? (b * 520 + p) : (b * 520 + 516 + (p - 4));
    float4 v = *(const float4*)s;
    __half2 h2[2];
    h2[0] = __float22half2_rn(make_float2(v.x, v.y));
    h2[1] = __float22half2_rn(make_float2(v.z, v.w));
    size_t o = (size_t)row * 512 + h;
    *(uint2*)(&g_P[0][l][0] + o) = *(uint2*)h2;
    *(uint2*)(&g_P[1][l][0] + o) = *(uint2*)h2;
}

// ================= host =================
extern "C" void kernel_launch(void* const* d_in, const int* in_sizes, int n_in,
                              void* d_out, int out_size)
{
    const float* inputs   = (const float*)d_in[0];
    const float* fwd_pads = (const float*)d_in[2];
    const float* bwd_pads = (const float*)d_in[3];
    const float* fwd_W    = (const float*)d_in[4];
    const float* fwd_bi   = (const float*)d_in[5];
    const float* bwd_W    = (const float*)d_in[6];
    const float* bwd_bi   = (const float*)d_in[7];
    const float* fwd_hw_W = (const float*)d_in[8];
    const float* fwd_hw_b = (const float*)d_in[9];
    const float* bwd_hw_W = (const float*)d_in[10];
    const float* bwd_hw_b = (const float*)d_in[11];
    float* out = (float*)d_out;

    cudaFuncSetAttribute(fused_kernel, cudaFuncAttributeMaxDynamicSharedMemorySize, DSM);

    zero_sync<<<9, 256>>>();
    prep_convW<<<dim3(1920,2), 256>>>(fwd_W, bwd_W);
    prep_hwW<<<dim3(1536,2), 256>>>(fwd_hw_W, bwd_hw_W);
    prep_act<<<8192, 256>>>(inputs);
    prep_pads<<<dim3(128,3), 256>>>(fwd_pads, bwd_pads);

    Args a{};
    a.bc_f = fwd_bi;   a.bc_b = bwd_bi;
    a.bh_f = fwd_hw_b; a.bh_b = bwd_hw_b;
    a.out = out;
    fused_kernel<<<3 * 5120, 256, DSM>>>(a);
}

// round 13
// speedup vs baseline: 3.9252x; 1.0127x over previous
#include <cuda_runtime.h>
#include <cuda_fp16.h>
#include <cstdint>

typedef unsigned int u32;
typedef unsigned long long u64;

#define Hd   512
#define SPd  520
#define MTr  16384
#define PSZ  (32*SPd*Hd)
#define INTOFF 2048
#define CWL  (512*2560)
#define HWL  (1024*512)

// ---------------- static device scratch ----------------
__device__ __half g_P[2][3][PSZ];    // conv inputs per [dir][layer], padded, pads prefilled
__device__ __half g_T[2][PSZ];       // conv output / hw1 input
__device__ __half g_U[2][PSZ];       // hw1 output / hw2 input
__device__ __half g_cW[2][3*CWL];    // conv weights [dir][layer][512 n][2560 k]
__device__ __half g_hW[2][6*HWL];    // hw weights   [dir][l*2+j][1024 q][512 k]

// scheduler: completion counters [layer][phase][z][mtile] + global ticket
__device__ int g_sync[3][3][2][128];
__device__ int g_tix;

// ---------------- helpers ----------------
__device__ __forceinline__ u32 s2u(const void* p) {
    u32 a; asm("{ .reg .u64 t; cvta.to.shared.u64 t, %1; cvt.u32.u64 %0, t; }"
               : "=r"(a) : "l"(p)); return a;
}
__device__ __forceinline__ void cp16(u32 d, const void* s) {
    asm volatile("cp.async.cg.shared.global [%0], [%1], 16;" :: "r"(d), "l"(s) : "memory");
}
__device__ __forceinline__ void ldsm4(u32* r, u32 a) {
    asm volatile("ldmatrix.sync.aligned.m8n8.x4.shared.b16 {%0,%1,%2,%3}, [%4];"
                 : "=r"(r[0]), "=r"(r[1]), "=r"(r[2]), "=r"(r[3]) : "r"(a));
}
__device__ __forceinline__ void mma16816(float* d, const u32* a, const u32* b) {
    asm volatile("mma.sync.aligned.m16n8k16.row.col.f32.f16.f16.f32 "
                 "{%0,%1,%2,%3}, {%4,%5,%6,%7}, {%8,%9}, {%0,%1,%2,%3};"
                 : "+f"(d[0]), "+f"(d[1]), "+f"(d[2]), "+f"(d[3])
                 : "r"(a[0]), "r"(a[1]), "r"(a[2]), "r"(a[3]), "r"(b[0]), "r"(b[1]));
}
__device__ __forceinline__ size_t crow(int r) {
    return (size_t)(r + ((r >> 9) << 3)) * Hd;   // conv-mapped padded row
}
__device__ __forceinline__ u32 swz(int row, int ch) {   // 64B-row XOR swizzle
    return (u32)(row * 64 + ((ch ^ ((row >> 1) & 3)) << 4));
}
__device__ __forceinline__ void dwait(int* c, int tgt) {
    while (atomicAdd(c, 0) < tgt) __nanosleep(64);
}

#define STAGE 16384            // per chunk: A 8KB + B 8KB
#define NSTG  6
#define DSM   (128 + NSTG*STAGE)   // 96.1KB; staging (67.7KB) unions in; occ2=192KB

struct Args {
    const float *bc_f, *bc_b;    // conv biases [3][512]
    const float *bh_f, *bh_b;    // hw biases   [6][1024]
    float* out;
};

// ============ fully-fused 3-layer kernel via global ticket queue ============
// ticket t: layer = t/5120, u = t%5120
//   u in [0,1024):    conv  z=u&1, n=(u>>1)&3, m=u>>3
//   u in [1024,3072): hw1   z=v&1, n=(v>>1)&7, m=v>>4   (v=u-1024)
//   u in [3072,5120): hw2   (v=u-3072, same decode)
// deps (all strictly older tickets -> deadlock-free by monotone draw order):
//   conv(l>=1,z,m): hw2(l-1)[z][m]==8; fwd also [m-1]==8 (if m%4!=0),
//                   bwd also [m+1]==8 (if m%4!=3)      (4-row K-window)
//   hw1(l,z,m): conv(l)[z][m]==4
//   hw2(l,z,m): hw1(l)[z][m]==8
__global__ __launch_bounds__(256, 2)
void fused_kernel(Args a)
{
    extern __shared__ char dsm[];
    const u32 base = (s2u(dsm) + 127) & ~127u;
    float* sstg = (float*)(dsm + (base - s2u(dsm)));   // UNION with pipeline stages

    __shared__ int s_t;
    const int tid = threadIdx.x;
    if (tid == 0) s_t = atomicAdd(&g_tix, 1);
    __syncthreads();
    const int t = s_t;

    const int layer = t / 5120;
    const int u = t - layer * 5120;
    int phase, m, n, z;
    if (u < 1024)      { phase = 0; z = u & 1; n = (u >> 1) & 3; m = u >> 3; }
    else if (u < 3072) { int v = u - 1024; phase = 1; z = v & 1; n = (v >> 1) & 7; m = v >> 4; }
    else               { int v = u - 3072; phase = 2; z = v & 1; n = (v >> 1) & 7; m = v >> 4; }

    int K;
    const __half *A, *W, *X = nullptr;
    const float* bias;
    __half* Y = nullptr; float* op = nullptr;
    if (phase == 0) {
        K = 2560;
        A = &g_P[z][layer][0] + (z ? 2048 : 0);      // fwd window off 0, bwd off W rows
        W = &g_cW[z][(size_t)layer * CWL];
        bias = (z ? a.bc_b : a.bc_f) + layer * 512;
        Y = &g_T[z][INTOFF];
    } else if (phase == 1) {
        K = 512;
        A = X = &g_T[z][INTOFF];
        W = &g_hW[z][(size_t)(layer * 2) * HWL];
        bias = (z ? a.bh_b : a.bh_f) + (size_t)(layer * 2) * 1024;
        Y = &g_U[z][INTOFF];
    } else {
        K = 512;
        A = X = &g_U[z][INTOFF];
        W = &g_hW[z][(size_t)(layer * 2 + 1) * HWL];
        bias = (z ? a.bh_b : a.bh_f) + (size_t)(layer * 2 + 1) * 1024;
        Y = (layer < 2) ? &g_P[z][layer + 1][INTOFF] : nullptr;
        op = a.out + (size_t)layer * MTr * 1024 + z * 512;
    }

    // ---- dependency wait (tid0 spins, broadcast via syncthreads) ----
    if (tid == 0) {
        if (phase == 0) {
            if (layer > 0) {
                dwait(&g_sync[layer - 1][2][z][m], 8);
                if (z == 0) { if ((m & 3) != 0) dwait(&g_sync[layer - 1][2][0][m - 1], 8); }
                else        { if ((m & 3) != 3) dwait(&g_sync[layer - 1][2][1][m + 1], 8); }
            }
        } else if (phase == 1) {
            dwait(&g_sync[layer][0][z][m], 4);
        } else {
            dwait(&g_sync[layer][1][z][m], 8);
        }
        __threadfence();
    }
    __syncthreads();

    const int NP   = K >> 6;                 // chunk-pairs (K/64)
    const int lane = tid & 31;
    const int wid  = tid >> 5;
    const int wm   = (wid >> 2) * 64;
    const int wn   = (wid & 3) * 32;
    const int m0   = m << 7;
    const int nb0  = n << 7;

    const __half* aSrc[2]; u32 aOff[2];
    const __half* bSrc[2]; u32 bOff[2];
#pragma unroll
    for (int it = 0; it < 2; it++) {
        int v = tid + it * 256;
        int row = v >> 2, ch = v & 3;
        aSrc[it] = A + crow(m0 + row) + ch * 8;
        aOff[it] = swz(row, ch);
        bSrc[it] = W + (size_t)(nb0 + row) * K + ch * 8;
        bOff[it] = 8192u + swz(row, ch);
    }

    // load one chunk into stage st (no commit)
    auto load_chunk = [&](int c, int st) {
        const u32 sb = base + (u32)(st * STAGE);
        const int kc = c * 32;
#pragma unroll
        for (int it = 0; it < 2; it++) cp16(sb + aOff[it], aSrc[it] + kc);
#pragma unroll
        for (int it = 0; it < 2; it++) cp16(sb + bOff[it], bSrc[it] + kc);
    };
    auto load_pair = [&](int p, int st) {   // chunks 2p, 2p+1 -> stages st, st+1
        load_chunk(2 * p, st);
        load_chunk(2 * p + 1, st + 1);
        asm volatile("cp.async.commit_group;" ::: "memory");
    };

    float acc[4][4][4];
#pragma unroll
    for (int i = 0; i < 4; i++)
#pragma unroll
        for (int j = 0; j < 4; j++)
#pragma unroll
            for (int q = 0; q < 4; q++) acc[i][j][q] = 0.f;

    load_pair(0, 0);
    load_pair(1, 2);

    const int ar = lane & 15;
    const int ac = lane >> 4;
    const int br = (lane & 7) + ((lane & 16) >> 1);
    const int bc = (lane >> 3) & 1;

    int cst = 0, lst = 4;                    // compute stage, load stage (even, mod 6)
    for (int p = 0; p < NP; p++) {
        asm volatile("cp.async.wait_group 1;" ::: "memory");
        __syncthreads();
        if (p + 2 < NP) load_pair(p + 2, lst);
        else            asm volatile("cp.async.commit_group;" ::: "memory");

#pragma unroll
        for (int h = 0; h < 2; h++) {        // two chunks of the pair
            const u32 sb = base + (u32)((cst + h) * STAGE);
#pragma unroll
            for (int s = 0; s < 2; s++) {
                u32 bfb[8], afr[4][4];
                ldsm4(&bfb[0], sb + 8192 + swz(wn + br, 2 * s + bc));
                ldsm4(&bfb[4], sb + 8192 + swz(wn + 16 + br, 2 * s + bc));
#pragma unroll
                for (int i = 0; i < 4; i++)
                    ldsm4(afr[i], sb + swz(wm + i * 16 + ar, 2 * s + ac));
#pragma unroll
                for (int i = 0; i < 4; i++)
#pragma unroll
                    for (int j = 0; j < 4; j++)
                        mma16816(acc[i][j], afr[i], &bfb[j * 2]);
            }
        }
        cst = (cst == 4) ? 0 : cst + 2;
        lst = (lst == 4) ? 0 : lst + 2;
    }

    // ---- stage accumulators to smem (pipeline smem now dead) ----
    __syncthreads();
#pragma unroll
    for (int i = 0; i < 4; i++)
#pragma unroll
        for (int j = 0; j < 4; j++) {
            int r0 = wm + i * 16 + (lane >> 2);
            int cc = wn + j * 8 + (lane & 3) * 2;
            *(float2*)&sstg[r0 * 132 + cc]       = make_float2(acc[i][j][0], acc[i][j][1]);
            *(float2*)&sstg[(r0 + 8) * 132 + cc] = make_float2(acc[i][j][2], acc[i][j][3]);
        }
    __syncthreads();

    // ---- fused, coalesced epilogue ----
    const int r  = tid >> 1;
    const int gr = m0 + r;

    if (phase == 0) {
        const int c0 = (tid & 1) * 64;
#pragma unroll
        for (int c8 = 0; c8 < 8; c8++) {
            const int cb = c0 + c8 * 8;
            __half2 hv[4];
#pragma unroll
            for (int tt = 0; tt < 4; tt++) {
                float v0 = fmaxf(sstg[r * 132 + cb + 2*tt]     + bias[nb0 + cb + 2*tt],     0.f);
                float v1 = fmaxf(sstg[r * 132 + cb + 2*tt + 1] + bias[nb0 + cb + 2*tt + 1], 0.f);
                hv[tt] = __float22half2_rn(make_float2(v0, v1));
            }
            *(uint4*)(Y + crow(gr) + nb0 + cb) = *(uint4*)hv;
        }
    } else {
        const int fbase = n * 64;
        const int fl0   = (tid & 1) * 32;
#pragma unroll
        for (int c8 = 0; c8 < 4; c8++) {
            const int fl = fl0 + c8 * 8;
            const int f  = fbase + fl;
            uint4 x4 = *(const uint4*)(X + crow(gr) + f);
            __half2 hv[4];
            float ov[8];
#pragma unroll
            for (int tt = 0; tt < 4; tt++) {
                float2 x2 = __half22float2(*(__half2*)&((u32*)&x4)[tt]);
                float nl0 = sstg[r * 132 + fl + 2*tt]       + bias[f + 2*tt];
                float nl1 = sstg[r * 132 + fl + 2*tt + 1]   + bias[f + 2*tt + 1];
                float gt0 = sstg[r * 132 + 64 + fl + 2*tt]     + bias[512 + f + 2*tt];
                float gt1 = sstg[r * 132 + 64 + fl + 2*tt + 1] + bias[512 + f + 2*tt + 1];
                float s0 = 1.f / (1.f + __expf(-gt0));
                float s1 = 1.f / (1.f + __expf(-gt1));
                float o0 = s0 * x2.x + (1.f - s0) * fmaxf(nl0, 0.f);
                float o1 = s1 * x2.y + (1.f - s1) * fmaxf(nl1, 0.f);
                hv[tt] = __float22half2_rn(make_float2(o0, o1));
                ov[2*tt] = o0; ov[2*tt + 1] = o1;
            }
            if (Y) *(uint4*)(Y + crow(gr) + f) = *(uint4*)hv;
            if (op) {
                *(float4*)(op + (size_t)gr * 1024 + f)     = *(float4*)&ov[0];
                *(float4*)(op + (size_t)gr * 1024 + f + 4) = *(float4*)&ov[4];
            }
        }
    }

    // ---- publish completion ----
    __threadfence();
    __syncthreads();
    if (tid == 0) atomicAdd(&g_sync[layer][phase][z][m], 1);
}

// ================= prep kernels =================
__global__ void prep_convW(const float* __restrict__ Wf, const float* __restrict__ Wb) {
    int gid = blockIdx.x * blockDim.x + threadIdx.x;
    const float* W = blockIdx.y ? Wb : Wf;
    __half* O = &g_cW[blockIdx.y][0];
    int w = gid >> 5;
    int lane = threadIdx.x & 31;
    int layer = w / (16 * 320); int rem = w % (16 * 320);
    int n = (rem / 320) * 32 + lane; int k0 = (rem % 320) * 8;
    const float* src = W + (size_t)layer * 2560 * 512 + (size_t)k0 * 512 + n;
    __half2 h2[4];
#pragma unroll
    for (int t = 0; t < 4; t++)
        h2[t] = __float22half2_rn(make_float2(src[(2*t) * 512], src[(2*t + 1) * 512]));
    size_t o = ((size_t)layer * 512 + n) * 2560 + k0;
    *(uint4*)(O + o) = *(uint4*)h2;
}

__global__ void prep_hwW(const float* __restrict__ Wf, const float* __restrict__ Wb) {
    int gid = blockIdx.x * blockDim.x + threadIdx.x;
    const float* W = blockIdx.y ? Wb : Wf;
    __half* O = &g_hW[blockIdx.y][0];
    int w = gid >> 5;
    int lane = threadIdx.x & 31;
    int lw = w / (32 * 64); int rem = w % (32 * 64);
    int np = (rem / 64) * 32 + lane; int k0 = (rem % 64) * 8;
    int f = (np < 512) ? np : (np - 512);
    int q = (f >> 6) * 128 + ((np < 512) ? (f & 63) : (64 + (f & 63)));
    const float* src = W + (size_t)lw * 512 * 1024 + (size_t)k0 * 1024 + np;
    __half2 h2[4];
#pragma unroll
    for (int t = 0; t < 4; t++)
        h2[t] = __float22half2_rn(make_float2(src[(2*t) * 1024], src[(2*t + 1) * 1024]));
    size_t o = ((size_t)lw * 1024 + q) * 512 + k0;
    *(uint4*)(O + o) = *(uint4*)h2;
}

__global__ void prep_act(const float* __restrict__ in) {
    int idx = blockIdx.x * 256 + threadIdx.x;
    // fold scheduler zeroing into this kernel (one fewer launch)
    if (idx < 3 * 3 * 2 * 128) ((int*)g_sync)[idx] = 0;
    if (idx == 0) g_tix = 0;
    int e = idx << 2;
    int r = e >> 9, h = e & 511;
    float4 v = *(const float4*)(in + e);
    __half2 h2[2];
    h2[0] = __float22half2_rn(make_float2(v.x, v.y));
    h2[1] = __float22half2_rn(make_float2(v.z, v.w));
    size_t o = crow(r) + h + INTOFF;
    *(uint2*)(&g_P[0][0][0] + o) = *(uint2*)h2;
    *(uint2*)(&g_P[1][0][0] + o) = *(uint2*)h2;
}

__global__ void prep_pads(const float* __restrict__ fp, const float* __restrict__ bp) {
    // blockIdx.y = layer; fill pad rows of g_P[0][l] and g_P[1][l]
    int l = blockIdx.y;
    int idx = blockIdx.x * 256 + threadIdx.x;
    int e = idx << 2;
    int b = e >> 12; int rem = e & 4095; int p = rem >> 9; int h = rem & 511;
    const float* s = (p < 4) ? (fp + (size_t)l * 2048 + p * 512 + h)
                             : (bp + (size_t)l * 2048 + (p - 4) * 512 + h);
    int row = (p < 4) ? (b * 520 + p) : (b * 520 + 516 + (p - 4));
    float4 v = *(const float4*)s;
    __half2 h2[2];
    h2[0] = __float22half2_rn(make_float2(v.x, v.y));
    h2[1] = __float22half2_rn(make_float2(v.z, v.w));
    size_t o = (size_t)row * 512 + h;
    *(uint2*)(&g_P[0][l][0] + o) = *(uint2*)h2;
    *(uint2*)(&g_P[1][l][0] + o) = *(uint2*)h2;
}

// ================= host =================
extern "C" void kernel_launch(void* const* d_in, const int* in_sizes, int n_in,
                              void* d_out, int out_size)
{
    const float* inputs   = (const float*)d_in[0];
    const float* fwd_pads = (const float*)d_in[2];
    const float* bwd_pads = (const float*)d_in[3];
    const float* fwd_W    = (const float*)d_in[4];
    const float* fwd_bi   = (const float*)d_in[5];
    const float* bwd_W    = (const float*)d_in[6];
    const float* bwd_bi   = (const float*)d_in[7];
    const float* fwd_hw_W = (const float*)d_in[8];
    const float* fwd_hw_b = (const float*)d_in[9];
    const float* bwd_hw_W = (const float*)d_in[10];
    const float* bwd_hw_b = (const float*)d_in[11];
    float* out = (float*)d_out;

    cudaFuncSetAttribute(fused_kernel, cudaFuncAttributeMaxDynamicSharedMemorySize, DSM);

    prep_act<<<8192, 256>>>(inputs);
    prep_convW<<<dim3(1920,2), 256>>>(fwd_W, bwd_W);
    prep_hwW<<<dim3(1536,2), 256>>>(fwd_hw_W, bwd_hw_W);
    prep_pads<<<dim3(128,3), 256>>>(fwd_pads, bwd_pads);

    Args a{};
    a.bc_f = fwd_bi;   a.bc_b = bwd_bi;
    a.bh_f = fwd_hw_b; a.bh_b = bwd_hw_b;
    a.out = out;
    fused_kernel<<<3 * 5120, 256, DSM>>>(a);
}